// round 1
// baseline (speedup 1.0000x reference)
#include <cuda_runtime.h>
#include <cuda_bf16.h>
#include <cstdint>

// Problem constants (fixed by the dataset)
constexpr int NN   = 100000;   // nodes
constexpr int NE   = 1600000;  // edges
constexpr int NG   = 64;       // graphs
constexpr int DIN  = 128;
constexpr int DH   = 256;      // hidden == out dim

// Scratch (device globals — no allocations allowed)
__device__ __align__(16) float g_deg [NN];
__device__ __align__(16) float g_dinv[NN];
__device__ __align__(16) float g_h   [(size_t)NN * DH];  // GEMM output
__device__ __align__(16) float g_a   [(size_t)NN * DH];  // aggregated / layer input
__device__ int   g_cnt[NG];

// ---------------------------------------------------------------------------
// degree init (self-loop = 1), zero graph counters
__global__ void deg_init_kernel() {
    int i = blockIdx.x * blockDim.x + threadIdx.x;
    if (i < NN) g_deg[i] = 1.0f;
    if (i < NG) g_cnt[i] = 0;
}

// count incoming edges on target nodes
__global__ void deg_count_kernel(const int* __restrict__ col) {
    int e = blockIdx.x * blockDim.x + threadIdx.x;
    if (e < NE) atomicAdd(&g_deg[col[e]], 1.0f);
}

__global__ void dinv_kernel() {
    int i = blockIdx.x * blockDim.x + threadIdx.x;
    if (i < NN) g_dinv[i] = rsqrtf(g_deg[i]);
}

// ---------------------------------------------------------------------------
// Tiled fp32 GEMM: C[M,N] = A[M,K] @ B[K,N]
// BM=128, BN=64, BK=16, 256 threads, thread tile 8x4
#define GBM 128
#define GBN 64
#define GBK 16
#define GTM 8
#define GTN 4

__global__ __launch_bounds__(256) void gemm_kernel(
    const float* __restrict__ A, const float* __restrict__ B,
    float* __restrict__ C, int M, int K, int N)
{
    __shared__ float As[GBK][GBM];
    __shared__ float Bs[GBK][GBN];

    int tid = threadIdx.x;
    int tx = tid % (GBN / GTN);   // 0..15
    int ty = tid / (GBN / GTN);   // 0..15
    int rowBase = blockIdx.y * GBM;
    int colBase = blockIdx.x * GBN;

    // loader mapping
    int aRow = tid / (GBK / 4);          // 0..63
    int aCol = (tid % (GBK / 4)) * 4;    // 0,4,8,12
    int bRow = tid / (GBN / 4);          // 0..15
    int bCol = (tid % (GBN / 4)) * 4;

    float acc[GTM][GTN];
#pragma unroll
    for (int i = 0; i < GTM; i++)
#pragma unroll
        for (int j = 0; j < GTN; j++) acc[i][j] = 0.0f;

    for (int k0 = 0; k0 < K; k0 += GBK) {
        // Load A tile (transposed into As[k][m])
#pragma unroll
        for (int i = 0; i < 2; i++) {
            int r  = aRow + i * 64;
            int gr = rowBase + r;
            float4 v = make_float4(0.f, 0.f, 0.f, 0.f);
            if (gr < M)
                v = *reinterpret_cast<const float4*>(A + (size_t)gr * K + k0 + aCol);
            As[aCol + 0][r] = v.x;
            As[aCol + 1][r] = v.y;
            As[aCol + 2][r] = v.z;
            As[aCol + 3][r] = v.w;
        }
        // Load B tile
        {
            float4 v = *reinterpret_cast<const float4*>(
                B + (size_t)(k0 + bRow) * N + colBase + bCol);
            *reinterpret_cast<float4*>(&Bs[bRow][bCol]) = v;
        }
        __syncthreads();

#pragma unroll
        for (int k = 0; k < GBK; k++) {
            float ra[GTM], rb[GTN];
#pragma unroll
            for (int i = 0; i < GTM; i++) ra[i] = As[k][ty * GTM + i];
#pragma unroll
            for (int j = 0; j < GTN; j++) rb[j] = Bs[k][tx * GTN + j];
#pragma unroll
            for (int i = 0; i < GTM; i++)
#pragma unroll
                for (int j = 0; j < GTN; j++)
                    acc[i][j] += ra[i] * rb[j];
        }
        __syncthreads();
    }

#pragma unroll
    for (int i = 0; i < GTM; i++) {
        int gr = rowBase + ty * GTM + i;
        if (gr < M) {
            float4 o = make_float4(acc[i][0], acc[i][1], acc[i][2], acc[i][3]);
            *reinterpret_cast<float4*>(C + (size_t)gr * N + colBase + tx * GTN) = o;
        }
    }
}

// ---------------------------------------------------------------------------
// a[n,:] = h[n,:] * dinv[n]^2   (self-loop contribution, also zero-initializes a)
__global__ void self_init_kernel() {
    int idx = blockIdx.x * blockDim.x + threadIdx.x;  // float4 index
    if (idx >= NN * (DH / 4)) return;
    int n = idx >> 6;  // DH/4 = 64
    float s = g_dinv[n];
    s = s * s;
    float4 v = reinterpret_cast<const float4*>(g_h)[idx];
    v.x *= s; v.y *= s; v.z *= s; v.w *= s;
    reinterpret_cast<float4*>(g_a)[idx] = v;
}

__device__ __forceinline__ void red_add_v4(float* addr, float x, float y, float z, float w) {
    asm volatile("red.global.add.v4.f32 [%0], {%1, %2, %3, %4};"
                 :: "l"(addr), "f"(x), "f"(y), "f"(z), "f"(w) : "memory");
}

// One warp per edge: a[c,:] += h[r,:] * dinv[r]*dinv[c]
__global__ __launch_bounds__(256) void scatter_kernel(
    const int* __restrict__ src, const int* __restrict__ dst)
{
    int warp = (blockIdx.x * blockDim.x + threadIdx.x) >> 5;
    int lane = threadIdx.x & 31;
    if (warp >= NE) return;
    int r = src[warp];
    int c = dst[warp];
    float w = g_dinv[r] * g_dinv[c];
    const float4* h4 = reinterpret_cast<const float4*>(g_h + (size_t)r * DH);
    float* ab = g_a + (size_t)c * DH;
#pragma unroll
    for (int j = 0; j < 2; j++) {
        int o = j * 32 + lane;           // float4 slot 0..63
        float4 v = h4[o];
        red_add_v4(ab + o * 4, v.x * w, v.y * w, v.z * w, v.w * w);
    }
}

// a = relu(a + bias)
__global__ void bias_relu_kernel(const float* __restrict__ bias) {
    int idx = blockIdx.x * blockDim.x + threadIdx.x;  // float4 index
    if (idx >= NN * (DH / 4)) return;
    int d4 = idx & 63;
    float4 b = reinterpret_cast<const float4*>(bias)[d4];
    float4 v = reinterpret_cast<float4*>(g_a)[idx];
    v.x = fmaxf(v.x + b.x, 0.f);
    v.y = fmaxf(v.y + b.y, 0.f);
    v.z = fmaxf(v.z + b.z, 0.f);
    v.w = fmaxf(v.w + b.w, 0.f);
    reinterpret_cast<float4*>(g_a)[idx] = v;
}

// ---------------------------------------------------------------------------
__global__ void zero_out_kernel(float* __restrict__ out) {
    int idx = blockIdx.x * blockDim.x + threadIdx.x;
    if (idx < NG * DH) out[idx] = 0.0f;
}

// batch is sorted: register-accumulate runs, flush on graph boundary
#define POOL_CHUNK 512
__global__ __launch_bounds__(256) void pool_kernel(
    const int* __restrict__ batch, float* __restrict__ out)
{
    __shared__ int sb[POOL_CHUNK];
    int start = blockIdx.x * POOL_CHUNK;
    int end = min(start + POOL_CHUNK, NN);
    int cnt = end - start;
    for (int i = threadIdx.x; i < cnt; i += blockDim.x) sb[i] = batch[start + i];
    __syncthreads();

    int d = threadIdx.x;  // 0..255
    int curg = sb[0];
    float acc = 0.0f;
    int run = 0;
    for (int n = 0; n < cnt; n++) {
        int g = sb[n];
        if (g != curg) {
            atomicAdd(&out[curg * DH + d], acc);
            if (d == 0) atomicAdd(&g_cnt[curg], run);
            acc = 0.0f; run = 0; curg = g;
        }
        acc += g_a[(size_t)(start + n) * DH + d];
        run++;
    }
    atomicAdd(&out[curg * DH + d], acc);
    if (d == 0) atomicAdd(&g_cnt[curg], run);
}

__global__ void divide_kernel(float* __restrict__ out) {
    int idx = blockIdx.x * blockDim.x + threadIdx.x;
    if (idx >= NG * DH) return;
    int g = idx >> 8;
    float c = (float)g_cnt[g];
    out[idx] = out[idx] / fmaxf(c, 1.0f);
}

// ---------------------------------------------------------------------------
extern "C" void kernel_launch(void* const* d_in, const int* in_sizes, int n_in,
                              void* d_out, int out_size)
{
    const float* x    = (const float*)d_in[0];   // [NN, 128]
    const int*   ei   = (const int*)  d_in[1];   // [2, NE]
    const int*   batch= (const int*)  d_in[2];   // [NN]
    const float* W1   = (const float*)d_in[3];   // [128, 256]
    const float* b1   = (const float*)d_in[4];   // [256]
    const float* W2   = (const float*)d_in[5];   // [256, 256]
    const float* b2   = (const float*)d_in[6];   // [256]
    float* out = (float*)d_out;                  // [64, 256]

    const int* src = ei;        // edge_index[0] = source
    const int* dst = ei + NE;   // edge_index[1] = target

    float* d_h; cudaGetSymbolAddress((void**)&d_h, g_h);
    float* d_a; cudaGetSymbolAddress((void**)&d_a, g_a);

    // degrees + normalization
    deg_init_kernel<<<(NN + 255) / 256, 256>>>();
    deg_count_kernel<<<(NE + 255) / 256, 256>>>(dst);
    dinv_kernel<<<(NN + 255) / 256, 256>>>();

    dim3 gemmBlock(256);
    dim3 gemmGrid1(DH / GBN, (NN + GBM - 1) / GBM);

    // ---- Layer 1 ----
    gemm_kernel<<<gemmGrid1, gemmBlock>>>(x, W1, d_h, NN, DIN, DH);
    self_init_kernel<<<(NN * (DH / 4) + 255) / 256, 256>>>();
    scatter_kernel<<<NE / 8, 256>>>(src, dst);
    bias_relu_kernel<<<(NN * (DH / 4) + 255) / 256, 256>>>(b1);

    // ---- Layer 2 ----
    gemm_kernel<<<gemmGrid1, gemmBlock>>>(d_a, W2, d_h, NN, DH, DH);
    self_init_kernel<<<(NN * (DH / 4) + 255) / 256, 256>>>();
    scatter_kernel<<<NE / 8, 256>>>(src, dst);
    bias_relu_kernel<<<(NN * (DH / 4) + 255) / 256, 256>>>(b2);

    // ---- Global mean pool ----
    zero_out_kernel<<<(NG * DH + 255) / 256, 256>>>(out);
    pool_kernel<<<(NN + POOL_CHUNK - 1) / POOL_CHUNK, 256>>>(batch, out);
    divide_kernel<<<(NG * DH + 255) / 256, 256>>>(out);
}

// round 2
// speedup vs baseline: 1.6539x; 1.6539x over previous
#include <cuda_runtime.h>
#include <cuda_bf16.h>
#include <cstdint>

// Problem constants (fixed by the dataset)
constexpr int NN   = 100000;   // nodes
constexpr int NE   = 1600000;  // edges
constexpr int NG   = 64;       // graphs
constexpr int DIN  = 128;
constexpr int DH   = 256;      // hidden == out dim

constexpr int SCHUNK = 1024;
constexpr int NBLK_SCAN = (NN + SCHUNK - 1) / SCHUNK;  // 98

// Scratch (device globals — no allocations allowed)
__device__ __align__(16) float g_dinv[NN];
__device__ __align__(16) float g_h   [(size_t)NN * DH];  // GEMM output h' = dinv*(hW)
__device__ __align__(16) float g_a   [(size_t)NN * DH];  // aggregated / layer input
__device__ int   g_cin [NN];          // in-degree (edges only)
__device__ int   g_off [NN];          // within-chunk exclusive scan
__device__ int   g_bsum[NBLK_SCAN];   // chunk totals
__device__ int   g_bsumex[NBLK_SCAN]; // exclusive scan of chunk totals
__device__ int   g_fill[NN];          // fill cursors
__device__ int   g_adj [NE];          // CSR adjacency (src nodes, grouped by dst)
__device__ int   g_cnt [NG];          // graph node counters

// ---------------------------------------------------------------------------
__global__ void zero_kernel() {
    int i = blockIdx.x * blockDim.x + threadIdx.x;
    if (i < NN) { g_cin[i] = 0; g_fill[i] = 0; }
    if (i < NG) g_cnt[i] = 0;
}

__global__ void hist_kernel(const int* __restrict__ dst) {
    int e = blockIdx.x * blockDim.x + threadIdx.x;
    if (e < NE) atomicAdd(&g_cin[dst[e]], 1);
}

__global__ void dinv_kernel() {
    int i = blockIdx.x * blockDim.x + threadIdx.x;
    if (i < NN) g_dinv[i] = rsqrtf((float)(g_cin[i] + 1));
}

// Block scan over 1024-element chunks (256 threads × 4 elems)
__global__ __launch_bounds__(256) void scan_block_kernel() {
    __shared__ int st[256];
    int base = blockIdx.x * SCHUNK;
    int tid = threadIdx.x;
    int v[4], pre[4];
    int s = 0;
#pragma unroll
    for (int i = 0; i < 4; i++) {
        int idx = base + tid * 4 + i;
        v[i] = (idx < NN) ? g_cin[idx] : 0;
        pre[i] = s;
        s += v[i];
    }
    st[tid] = s;
    __syncthreads();
#pragma unroll
    for (int off = 1; off < 256; off <<= 1) {
        int x = (tid >= off) ? st[tid - off] : 0;
        __syncthreads();
        st[tid] += x;
        __syncthreads();
    }
    int excl = st[tid] - s;
#pragma unroll
    for (int i = 0; i < 4; i++) {
        int idx = base + tid * 4 + i;
        if (idx < NN) g_off[idx] = excl + pre[i];
    }
    if (tid == 255) g_bsum[blockIdx.x] = st[255];
}

__global__ void scan_top_kernel() {
    if (threadIdx.x == 0 && blockIdx.x == 0) {
        int run = 0;
        for (int b = 0; b < NBLK_SCAN; b++) {
            int t = g_bsum[b];
            g_bsumex[b] = run;
            run += t;
        }
    }
}

__global__ void fill_kernel(const int* __restrict__ src, const int* __restrict__ dst) {
    int e = blockIdx.x * blockDim.x + threadIdx.x;
    if (e >= NE) return;
    int c = dst[e];
    int pos = g_off[c] + g_bsumex[c >> 10] + atomicAdd(&g_fill[c], 1);
    g_adj[pos] = src[e];
}

// ---------------------------------------------------------------------------
// Tiled fp32 GEMM with row-scale epilogue: C[m,:] = dinv[m] * (A[m,:] @ B)
#define GBM 128
#define GBN 64
#define GBK 16
#define GTM 8
#define GTN 4

__global__ __launch_bounds__(256) void gemm_kernel(
    const float* __restrict__ A, const float* __restrict__ B,
    float* __restrict__ C, int M, int K, int N)
{
    __shared__ float As[GBK][GBM];
    __shared__ float Bs[GBK][GBN];

    int tid = threadIdx.x;
    int tx = tid % (GBN / GTN);
    int ty = tid / (GBN / GTN);
    int rowBase = blockIdx.y * GBM;
    int colBase = blockIdx.x * GBN;

    int aRow = tid / (GBK / 4);
    int aCol = (tid % (GBK / 4)) * 4;
    int bRow = tid / (GBN / 4);
    int bCol = (tid % (GBN / 4)) * 4;

    float acc[GTM][GTN];
#pragma unroll
    for (int i = 0; i < GTM; i++)
#pragma unroll
        for (int j = 0; j < GTN; j++) acc[i][j] = 0.0f;

    for (int k0 = 0; k0 < K; k0 += GBK) {
#pragma unroll
        for (int i = 0; i < 2; i++) {
            int r  = aRow + i * 64;
            int gr = rowBase + r;
            float4 v = make_float4(0.f, 0.f, 0.f, 0.f);
            if (gr < M)
                v = *reinterpret_cast<const float4*>(A + (size_t)gr * K + k0 + aCol);
            As[aCol + 0][r] = v.x;
            As[aCol + 1][r] = v.y;
            As[aCol + 2][r] = v.z;
            As[aCol + 3][r] = v.w;
        }
        {
            float4 v = *reinterpret_cast<const float4*>(
                B + (size_t)(k0 + bRow) * N + colBase + bCol);
            *reinterpret_cast<float4*>(&Bs[bRow][bCol]) = v;
        }
        __syncthreads();

#pragma unroll
        for (int k = 0; k < GBK; k++) {
            float ra[GTM], rb[GTN];
#pragma unroll
            for (int i = 0; i < GTM; i++) ra[i] = As[k][ty * GTM + i];
#pragma unroll
            for (int j = 0; j < GTN; j++) rb[j] = Bs[k][tx * GTN + j];
#pragma unroll
            for (int i = 0; i < GTM; i++)
#pragma unroll
                for (int j = 0; j < GTN; j++)
                    acc[i][j] += ra[i] * rb[j];
        }
        __syncthreads();
    }

#pragma unroll
    for (int i = 0; i < GTM; i++) {
        int gr = rowBase + ty * GTM + i;
        if (gr < M) {
            float s = g_dinv[gr];
            float4 o = make_float4(acc[i][0] * s, acc[i][1] * s,
                                   acc[i][2] * s, acc[i][3] * s);
            *reinterpret_cast<float4*>(C + (size_t)gr * N + colBase + tx * GTN) = o;
        }
    }
}

// ---------------------------------------------------------------------------
// CSR gather aggregation, fused self-loop + bias + ReLU.
// One warp per node; lane handles float4 slots {lane, lane+32} (8 floats).
// a[c] = relu(dinv[c] * (h'[c] + sum_{r in in(c)} h'[r]) + b)
__global__ __launch_bounds__(256) void aggregate_kernel(const float* __restrict__ bias) {
    int node = (blockIdx.x * blockDim.x + threadIdx.x) >> 5;
    int lane = threadIdx.x & 31;
    if (node >= NN) return;

    const float4* h4 = reinterpret_cast<const float4*>(g_h);
    size_t rb = (size_t)node * (DH / 4);
    float4 a0 = h4[rb + lane];
    float4 a1 = h4[rb + 32 + lane];

    int start = g_off[node] + g_bsumex[node >> 10];
    int cnt = g_cin[node];

    int j = 0;
    for (; j + 2 <= cnt; j += 2) {
        int r0 = g_adj[start + j];
        int r1 = g_adj[start + j + 1];
        size_t rb0 = (size_t)r0 * (DH / 4);
        size_t rb1 = (size_t)r1 * (DH / 4);
        float4 v0 = h4[rb0 + lane];
        float4 v1 = h4[rb0 + 32 + lane];
        float4 w0 = h4[rb1 + lane];
        float4 w1 = h4[rb1 + 32 + lane];
        a0.x += v0.x + w0.x; a0.y += v0.y + w0.y;
        a0.z += v0.z + w0.z; a0.w += v0.w + w0.w;
        a1.x += v1.x + w1.x; a1.y += v1.y + w1.y;
        a1.z += v1.z + w1.z; a1.w += v1.w + w1.w;
    }
    if (j < cnt) {
        int r0 = g_adj[start + j];
        size_t rb0 = (size_t)r0 * (DH / 4);
        float4 v0 = h4[rb0 + lane];
        float4 v1 = h4[rb0 + 32 + lane];
        a0.x += v0.x; a0.y += v0.y; a0.z += v0.z; a0.w += v0.w;
        a1.x += v1.x; a1.y += v1.y; a1.z += v1.z; a1.w += v1.w;
    }

    float dc = g_dinv[node];
    const float4* b4 = reinterpret_cast<const float4*>(bias);
    float4 b0 = b4[lane];
    float4 b1 = b4[32 + lane];
    float4 o0, o1;
    o0.x = fmaxf(fmaf(a0.x, dc, b0.x), 0.f);
    o0.y = fmaxf(fmaf(a0.y, dc, b0.y), 0.f);
    o0.z = fmaxf(fmaf(a0.z, dc, b0.z), 0.f);
    o0.w = fmaxf(fmaf(a0.w, dc, b0.w), 0.f);
    o1.x = fmaxf(fmaf(a1.x, dc, b1.x), 0.f);
    o1.y = fmaxf(fmaf(a1.y, dc, b1.y), 0.f);
    o1.z = fmaxf(fmaf(a1.z, dc, b1.z), 0.f);
    o1.w = fmaxf(fmaf(a1.w, dc, b1.w), 0.f);
    float4* out4 = reinterpret_cast<float4*>(g_a);
    out4[rb + lane] = o0;
    out4[rb + 32 + lane] = o1;
}

// ---------------------------------------------------------------------------
__global__ void zero_out_kernel(float* __restrict__ out) {
    int idx = blockIdx.x * blockDim.x + threadIdx.x;
    if (idx < NG * DH) out[idx] = 0.0f;
}

#define POOL_CHUNK 512
__global__ __launch_bounds__(256) void pool_kernel(
    const int* __restrict__ batch, float* __restrict__ out)
{
    __shared__ int sb[POOL_CHUNK];
    int start = blockIdx.x * POOL_CHUNK;
    int end = min(start + POOL_CHUNK, NN);
    int cnt = end - start;
    for (int i = threadIdx.x; i < cnt; i += blockDim.x) sb[i] = batch[start + i];
    __syncthreads();

    int d = threadIdx.x;
    int curg = sb[0];
    float acc = 0.0f;
    int run = 0;
    for (int n = 0; n < cnt; n++) {
        int g = sb[n];
        if (g != curg) {
            atomicAdd(&out[curg * DH + d], acc);
            if (d == 0) atomicAdd(&g_cnt[curg], run);
            acc = 0.0f; run = 0; curg = g;
        }
        acc += g_a[(size_t)(start + n) * DH + d];
        run++;
    }
    atomicAdd(&out[curg * DH + d], acc);
    if (d == 0) atomicAdd(&g_cnt[curg], run);
}

__global__ void divide_kernel(float* __restrict__ out) {
    int idx = blockIdx.x * blockDim.x + threadIdx.x;
    if (idx >= NG * DH) return;
    int g = idx >> 8;
    float c = (float)g_cnt[g];
    out[idx] = out[idx] / fmaxf(c, 1.0f);
}

// ---------------------------------------------------------------------------
extern "C" void kernel_launch(void* const* d_in, const int* in_sizes, int n_in,
                              void* d_out, int out_size)
{
    const float* x    = (const float*)d_in[0];   // [NN, 128]
    const int*   ei   = (const int*)  d_in[1];   // [2, NE]
    const int*   batch= (const int*)  d_in[2];   // [NN]
    const float* W1   = (const float*)d_in[3];   // [128, 256]
    const float* b1   = (const float*)d_in[4];   // [256]
    const float* W2   = (const float*)d_in[5];   // [256, 256]
    const float* b2   = (const float*)d_in[6];   // [256]
    float* out = (float*)d_out;                  // [64, 256]

    const int* src = ei;        // edge_index[0] = source
    const int* dst = ei + NE;   // edge_index[1] = target

    float* d_h; cudaGetSymbolAddress((void**)&d_h, g_h);
    float* d_a; cudaGetSymbolAddress((void**)&d_a, g_a);

    // ---- CSR build + normalization ----
    zero_kernel<<<(NN + 255) / 256, 256>>>();
    hist_kernel<<<(NE + 255) / 256, 256>>>(dst);
    dinv_kernel<<<(NN + 255) / 256, 256>>>();
    scan_block_kernel<<<NBLK_SCAN, 256>>>();
    scan_top_kernel<<<1, 32>>>();
    fill_kernel<<<(NE + 255) / 256, 256>>>(src, dst);

    dim3 gemmBlock(256);
    dim3 gemmGrid(DH / GBN, (NN + GBM - 1) / GBM);
    int aggGrid = (NN * 32 + 255) / 256;

    // ---- Layer 1 ----
    gemm_kernel<<<gemmGrid, gemmBlock>>>(x, W1, d_h, NN, DIN, DH);
    aggregate_kernel<<<aggGrid, 256>>>(b1);

    // ---- Layer 2 ----
    gemm_kernel<<<gemmGrid, gemmBlock>>>(d_a, W2, d_h, NN, DH, DH);
    aggregate_kernel<<<aggGrid, 256>>>(b2);

    // ---- Global mean pool ----
    zero_out_kernel<<<(NG * DH + 255) / 256, 256>>>(out);
    pool_kernel<<<(NN + POOL_CHUNK - 1) / POOL_CHUNK, 256>>>(batch, out);
    divide_kernel<<<(NG * DH + 255) / 256, 256>>>(out);
}

// round 3
// speedup vs baseline: 2.4296x; 1.4690x over previous
#include <cuda_runtime.h>
#include <cuda_bf16.h>
#include <cstdint>

// Problem constants (fixed by the dataset)
constexpr int NN   = 100000;   // nodes
constexpr int NE   = 1600000;  // edges
constexpr int NG   = 64;       // graphs
constexpr int DIN  = 128;
constexpr int DH   = 256;      // hidden == out dim

constexpr int SCHUNK = 1024;
constexpr int NBLK_SCAN = (NN + SCHUNK - 1) / SCHUNK;  // 98

// Scratch (device globals — no allocations allowed)
__device__ __align__(16) float g_dinv[NN];
__device__ __align__(16) float g_h   [(size_t)NN * DH];  // GEMM output h' = dinv*(hW)
__device__ __align__(16) float g_a   [(size_t)NN * DH];  // aggregated / layer input
__device__ int   g_cin [NN];          // in-degree (edges only)
__device__ int   g_off [NN];          // within-chunk exclusive scan
__device__ int   g_bsum[NBLK_SCAN];   // chunk totals
__device__ int   g_bsumex[NBLK_SCAN]; // exclusive scan of chunk totals
__device__ int   g_fill[NN];          // fill cursors
__device__ int   g_adj [NE];          // CSR adjacency (src nodes, grouped by dst)
__device__ int   g_cnt [NG];          // graph node counters

// ---------------------------------------------------------------------------
__global__ void zero_kernel() {
    int i = blockIdx.x * blockDim.x + threadIdx.x;
    if (i < NN) { g_cin[i] = 0; g_fill[i] = 0; }
    if (i < NG) g_cnt[i] = 0;
}

__global__ void hist_kernel(const int* __restrict__ dst) {
    int e = blockIdx.x * blockDim.x + threadIdx.x;
    if (e < NE) atomicAdd(&g_cin[dst[e]], 1);
}

__global__ void dinv_kernel() {
    int i = blockIdx.x * blockDim.x + threadIdx.x;
    if (i < NN) g_dinv[i] = rsqrtf((float)(g_cin[i] + 1));
}

// Block scan over 1024-element chunks (256 threads × 4 elems)
__global__ __launch_bounds__(256) void scan_block_kernel() {
    __shared__ int st[256];
    int base = blockIdx.x * SCHUNK;
    int tid = threadIdx.x;
    int v[4], pre[4];
    int s = 0;
#pragma unroll
    for (int i = 0; i < 4; i++) {
        int idx = base + tid * 4 + i;
        v[i] = (idx < NN) ? g_cin[idx] : 0;
        pre[i] = s;
        s += v[i];
    }
    st[tid] = s;
    __syncthreads();
#pragma unroll
    for (int off = 1; off < 256; off <<= 1) {
        int x = (tid >= off) ? st[tid - off] : 0;
        __syncthreads();
        st[tid] += x;
        __syncthreads();
    }
    int excl = st[tid] - s;
#pragma unroll
    for (int i = 0; i < 4; i++) {
        int idx = base + tid * 4 + i;
        if (idx < NN) g_off[idx] = excl + pre[i];
    }
    if (tid == 255) g_bsum[blockIdx.x] = st[255];
}

__global__ void scan_top_kernel() {
    if (threadIdx.x == 0 && blockIdx.x == 0) {
        int run = 0;
        for (int b = 0; b < NBLK_SCAN; b++) {
            int t = g_bsum[b];
            g_bsumex[b] = run;
            run += t;
        }
    }
}

__global__ void fill_kernel(const int* __restrict__ src, const int* __restrict__ dst) {
    int e = blockIdx.x * blockDim.x + threadIdx.x;
    if (e >= NE) return;
    int c = dst[e];
    int pos = g_off[c] + g_bsumex[c >> 10] + atomicAdd(&g_fill[c], 1);
    g_adj[pos] = src[e];
}

// ---------------------------------------------------------------------------
// Tensor-core tf32 GEMM with row-scale epilogue: C[m,:] = dinv[m] * (A[m,:] @ B)
// CTA tile 128x128, BK=16, 8 warps (warp tile 64x32), mma.m16n8k8.tf32,
// cp.async double-buffered shared memory.
#define TBM 128
#define TBN 128
#define TBK 16
#define APAD 20    // floats per A smem row (conflict-free for frag loads)
#define BPAD 136   // floats per B smem row

__device__ __forceinline__ uint32_t f2tf32(float f) {
    uint32_t u;
    asm("cvt.rna.tf32.f32 %0, %1;" : "=r"(u) : "f"(f));
    return u;
}

__device__ __forceinline__ void mma_tf32(float* d,
    uint32_t a0, uint32_t a1, uint32_t a2, uint32_t a3,
    uint32_t b0, uint32_t b1)
{
    asm volatile("mma.sync.aligned.m16n8k8.row.col.f32.tf32.tf32.f32 "
        "{%0,%1,%2,%3}, {%4,%5,%6,%7}, {%8,%9}, {%0,%1,%2,%3};\n"
        : "+f"(d[0]), "+f"(d[1]), "+f"(d[2]), "+f"(d[3])
        : "r"(a0), "r"(a1), "r"(a2), "r"(a3), "r"(b0), "r"(b1));
}

__global__ __launch_bounds__(256) void gemm_tc_kernel(
    const float* __restrict__ A, const float* __restrict__ B,
    float* __restrict__ C, int M, int K, int N)
{
    __shared__ float As[2][TBM * APAD];
    __shared__ float Bs[2][TBK * BPAD];

    int tid  = threadIdx.x;
    int lane = tid & 31;
    int warp = tid >> 5;
    int warpM = warp & 1;    // 0..1  (64 rows each)
    int warpN = warp >> 1;   // 0..3  (32 cols each)
    int rowBase = blockIdx.y * TBM;
    int colBase = blockIdx.x * TBN;

    // loader mapping
    int aRow = tid >> 2;          // 0..63
    int aC4  = (tid & 3) * 4;     // 0,4,8,12
    int bRow = tid >> 5;          // 0..7
    int bC4  = (tid & 31) * 4;    // 0..124

    float acc[4][4][4];
#pragma unroll
    for (int mt = 0; mt < 4; mt++)
#pragma unroll
        for (int nt = 0; nt < 4; nt++)
#pragma unroll
            for (int i = 0; i < 4; i++) acc[mt][nt][i] = 0.0f;

    auto load_tiles = [&](int s, int k0) {
#pragma unroll
        for (int i = 0; i < 2; i++) {
            int r = aRow + i * 64;
            int gr = rowBase + r;
            const float* src = A + (size_t)(gr < M ? gr : 0) * K + k0 + aC4;
            uint32_t dst = (uint32_t)__cvta_generic_to_shared(&As[s][r * APAD + aC4]);
            int sz = (gr < M) ? 16 : 0;
            asm volatile("cp.async.cg.shared.global [%0], [%1], 16, %2;\n"
                         :: "r"(dst), "l"(src), "r"(sz));
        }
#pragma unroll
        for (int i = 0; i < 2; i++) {
            int r = bRow + i * 8;
            const float* src = B + (size_t)(k0 + r) * N + colBase + bC4;
            uint32_t dst = (uint32_t)__cvta_generic_to_shared(&Bs[s][r * BPAD + bC4]);
            asm volatile("cp.async.cg.shared.global [%0], [%1], 16;\n"
                         :: "r"(dst), "l"(src));
        }
    };

    auto compute = [&](int s) {
        int r = lane >> 2;
        int c = lane & 3;
#pragma unroll
        for (int kg = 0; kg < 2; kg++) {
            uint32_t af[4][4], bf[4][2];
#pragma unroll
            for (int mt = 0; mt < 4; mt++) {
                int mb = warpM * 64 + mt * 16;
                float x0 = As[s][(mb + r)     * APAD + kg * 8 + c];
                float x1 = As[s][(mb + r + 8) * APAD + kg * 8 + c];
                float x2 = As[s][(mb + r)     * APAD + kg * 8 + c + 4];
                float x3 = As[s][(mb + r + 8) * APAD + kg * 8 + c + 4];
                af[mt][0] = f2tf32(x0); af[mt][1] = f2tf32(x1);
                af[mt][2] = f2tf32(x2); af[mt][3] = f2tf32(x3);
            }
#pragma unroll
            for (int nt = 0; nt < 4; nt++) {
                int nb = warpN * 32 + nt * 8;
                float y0 = Bs[s][(kg * 8 + c)     * BPAD + nb + r];
                float y1 = Bs[s][(kg * 8 + c + 4) * BPAD + nb + r];
                bf[nt][0] = f2tf32(y0); bf[nt][1] = f2tf32(y1);
            }
#pragma unroll
            for (int mt = 0; mt < 4; mt++)
#pragma unroll
                for (int nt = 0; nt < 4; nt++)
                    mma_tf32(acc[mt][nt],
                             af[mt][0], af[mt][1], af[mt][2], af[mt][3],
                             bf[nt][0], bf[nt][1]);
        }
    };

    load_tiles(0, 0);
    asm volatile("cp.async.commit_group;\n");
    int buf = 0;
    for (int k0 = TBK; k0 < K; k0 += TBK) {
        load_tiles(buf ^ 1, k0);
        asm volatile("cp.async.commit_group;\n");
        asm volatile("cp.async.wait_group 1;\n");
        __syncthreads();
        compute(buf);
        __syncthreads();
        buf ^= 1;
    }
    asm volatile("cp.async.wait_group 0;\n");
    __syncthreads();
    compute(buf);

    // Epilogue: scale rows by dinv and store
    int r = lane >> 2;
    int c = lane & 3;
#pragma unroll
    for (int mt = 0; mt < 4; mt++) {
        int grow0 = rowBase + warpM * 64 + mt * 16 + r;
        int grow1 = grow0 + 8;
        float s0 = (grow0 < M) ? g_dinv[grow0] : 0.0f;
        float s1 = (grow1 < M) ? g_dinv[grow1] : 0.0f;
#pragma unroll
        for (int nt = 0; nt < 4; nt++) {
            int gcol = colBase + warpN * 32 + nt * 8 + c * 2;
            if (grow0 < M) {
                float2 v = make_float2(acc[mt][nt][0] * s0, acc[mt][nt][1] * s0);
                *reinterpret_cast<float2*>(C + (size_t)grow0 * N + gcol) = v;
            }
            if (grow1 < M) {
                float2 v = make_float2(acc[mt][nt][2] * s1, acc[mt][nt][3] * s1);
                *reinterpret_cast<float2*>(C + (size_t)grow1 * N + gcol) = v;
            }
        }
    }
}

// ---------------------------------------------------------------------------
// CSR gather aggregation, fused self-loop + bias + ReLU.
// One warp per node; lane handles float4 slots {lane, lane+32} (8 floats).
// a[c] = relu(dinv[c] * (h'[c] + sum_{r in in(c)} h'[r]) + b)
__global__ __launch_bounds__(256) void aggregate_kernel(const float* __restrict__ bias) {
    int node = (blockIdx.x * blockDim.x + threadIdx.x) >> 5;
    int lane = threadIdx.x & 31;
    if (node >= NN) return;

    const float4* h4 = reinterpret_cast<const float4*>(g_h);
    size_t rb = (size_t)node * (DH / 4);
    float4 a0 = h4[rb + lane];
    float4 a1 = h4[rb + 32 + lane];

    int start = g_off[node] + g_bsumex[node >> 10];
    int cnt = g_cin[node];

    int j = 0;
    for (; j + 2 <= cnt; j += 2) {
        int r0 = g_adj[start + j];
        int r1 = g_adj[start + j + 1];
        size_t rb0 = (size_t)r0 * (DH / 4);
        size_t rb1 = (size_t)r1 * (DH / 4);
        float4 v0 = h4[rb0 + lane];
        float4 v1 = h4[rb0 + 32 + lane];
        float4 w0 = h4[rb1 + lane];
        float4 w1 = h4[rb1 + 32 + lane];
        a0.x += v0.x + w0.x; a0.y += v0.y + w0.y;
        a0.z += v0.z + w0.z; a0.w += v0.w + w0.w;
        a1.x += v1.x + w1.x; a1.y += v1.y + w1.y;
        a1.z += v1.z + w1.z; a1.w += v1.w + w1.w;
    }
    if (j < cnt) {
        int r0 = g_adj[start + j];
        size_t rb0 = (size_t)r0 * (DH / 4);
        float4 v0 = h4[rb0 + lane];
        float4 v1 = h4[rb0 + 32 + lane];
        a0.x += v0.x; a0.y += v0.y; a0.z += v0.z; a0.w += v0.w;
        a1.x += v1.x; a1.y += v1.y; a1.z += v1.z; a1.w += v1.w;
    }

    float dc = g_dinv[node];
    const float4* b4 = reinterpret_cast<const float4*>(bias);
    float4 b0 = b4[lane];
    float4 b1 = b4[32 + lane];
    float4 o0, o1;
    o0.x = fmaxf(fmaf(a0.x, dc, b0.x), 0.f);
    o0.y = fmaxf(fmaf(a0.y, dc, b0.y), 0.f);
    o0.z = fmaxf(fmaf(a0.z, dc, b0.z), 0.f);
    o0.w = fmaxf(fmaf(a0.w, dc, b0.w), 0.f);
    o1.x = fmaxf(fmaf(a1.x, dc, b1.x), 0.f);
    o1.y = fmaxf(fmaf(a1.y, dc, b1.y), 0.f);
    o1.z = fmaxf(fmaf(a1.z, dc, b1.z), 0.f);
    o1.w = fmaxf(fmaf(a1.w, dc, b1.w), 0.f);
    float4* out4 = reinterpret_cast<float4*>(g_a);
    out4[rb + lane] = o0;
    out4[rb + 32 + lane] = o1;
}

// ---------------------------------------------------------------------------
__global__ void zero_out_kernel(float* __restrict__ out) {
    int idx = blockIdx.x * blockDim.x + threadIdx.x;
    if (idx < NG * DH) out[idx] = 0.0f;
}

#define POOL_CHUNK 512
__global__ __launch_bounds__(256) void pool_kernel(
    const int* __restrict__ batch, float* __restrict__ out)
{
    __shared__ int sb[POOL_CHUNK];
    int start = blockIdx.x * POOL_CHUNK;
    int end = min(start + POOL_CHUNK, NN);
    int cnt = end - start;
    for (int i = threadIdx.x; i < cnt; i += blockDim.x) sb[i] = batch[start + i];
    __syncthreads();

    int d = threadIdx.x;
    int curg = sb[0];
    float acc = 0.0f;
    int run = 0;
    for (int n = 0; n < cnt; n++) {
        int g = sb[n];
        if (g != curg) {
            atomicAdd(&out[curg * DH + d], acc);
            if (d == 0) atomicAdd(&g_cnt[curg], run);
            acc = 0.0f; run = 0; curg = g;
        }
        acc += g_a[(size_t)(start + n) * DH + d];
        run++;
    }
    atomicAdd(&out[curg * DH + d], acc);
    if (d == 0) atomicAdd(&g_cnt[curg], run);
}

__global__ void divide_kernel(float* __restrict__ out) {
    int idx = blockIdx.x * blockDim.x + threadIdx.x;
    if (idx >= NG * DH) return;
    int g = idx >> 8;
    float c = (float)g_cnt[g];
    out[idx] = out[idx] / fmaxf(c, 1.0f);
}

// ---------------------------------------------------------------------------
extern "C" void kernel_launch(void* const* d_in, const int* in_sizes, int n_in,
                              void* d_out, int out_size)
{
    const float* x    = (const float*)d_in[0];   // [NN, 128]
    const int*   ei   = (const int*)  d_in[1];   // [2, NE]
    const int*   batch= (const int*)  d_in[2];   // [NN]
    const float* W1   = (const float*)d_in[3];   // [128, 256]
    const float* b1   = (const float*)d_in[4];   // [256]
    const float* W2   = (const float*)d_in[5];   // [256, 256]
    const float* b2   = (const float*)d_in[6];   // [256]
    float* out = (float*)d_out;                  // [64, 256]

    const int* src = ei;        // edge_index[0] = source
    const int* dst = ei + NE;   // edge_index[1] = target

    float* d_h; cudaGetSymbolAddress((void**)&d_h, g_h);
    float* d_a; cudaGetSymbolAddress((void**)&d_a, g_a);

    // ---- CSR build + normalization ----
    zero_kernel<<<(NN + 255) / 256, 256>>>();
    hist_kernel<<<(NE + 255) / 256, 256>>>(dst);
    dinv_kernel<<<(NN + 255) / 256, 256>>>();
    scan_block_kernel<<<NBLK_SCAN, 256>>>();
    scan_top_kernel<<<1, 32>>>();
    fill_kernel<<<(NE + 255) / 256, 256>>>(src, dst);

    dim3 gemmBlock(256);
    dim3 gemmGrid(DH / TBN, (NN + TBM - 1) / TBM);   // (2, 782)
    int aggGrid = (NN * 32 + 255) / 256;

    // ---- Layer 1 ----
    gemm_tc_kernel<<<gemmGrid, gemmBlock>>>(x, W1, d_h, NN, DIN, DH);
    aggregate_kernel<<<aggGrid, 256>>>(b1);

    // ---- Layer 2 ----
    gemm_tc_kernel<<<gemmGrid, gemmBlock>>>(d_a, W2, d_h, NN, DH, DH);
    aggregate_kernel<<<aggGrid, 256>>>(b2);

    // ---- Global mean pool ----
    zero_out_kernel<<<(NG * DH + 255) / 256, 256>>>(out);
    pool_kernel<<<(NN + POOL_CHUNK - 1) / POOL_CHUNK, 256>>>(batch, out);
    divide_kernel<<<(NG * DH + 255) / 256, 256>>>(out);
}

// round 4
// speedup vs baseline: 2.6331x; 1.0838x over previous
#include <cuda_runtime.h>
#include <cuda_bf16.h>
#include <cstdint>

// Problem constants (fixed by the dataset)
constexpr int NN   = 100000;   // nodes
constexpr int NE   = 1600000;  // edges
constexpr int NG   = 64;       // graphs
constexpr int DIN  = 128;
constexpr int DH   = 256;      // hidden == out dim

constexpr int SCHUNK = 1024;
constexpr int NBLK_SCAN = (NN + SCHUNK - 1) / SCHUNK;  // 98

// Scratch (device globals — no allocations allowed)
__device__ __align__(16) float g_dinv[NN];
__device__ __align__(16) float g_h   [(size_t)NN * DH];  // aggregate outputs (y1,y2)
__device__ __align__(16) float g_a   [(size_t)NN * DH];  // GEMM outputs (a1,a2)
__device__ int   g_cin [NN];          // in-degree (edges only)
__device__ int   g_off [NN];          // within-chunk exclusive scan
__device__ int   g_bsum[NBLK_SCAN];   // chunk totals
__device__ int   g_bsumex[NBLK_SCAN]; // exclusive scan of chunk totals
__device__ int   g_fill[NN];          // fill cursors
__device__ int   g_adj [NE];          // CSR adjacency (src nodes, grouped by dst)
__device__ int   g_cnt [NG];          // graph node counters

// ---------------------------------------------------------------------------
__global__ void zero_kernel() {
    int i = blockIdx.x * blockDim.x + threadIdx.x;
    if (i < NN) { g_cin[i] = 0; g_fill[i] = 0; }
    if (i < NG) g_cnt[i] = 0;
}

__global__ void hist_kernel(const int* __restrict__ dst) {
    int e = blockIdx.x * blockDim.x + threadIdx.x;
    if (e < NE) atomicAdd(&g_cin[dst[e]], 1);
}

__global__ void dinv_kernel() {
    int i = blockIdx.x * blockDim.x + threadIdx.x;
    if (i < NN) g_dinv[i] = rsqrtf((float)(g_cin[i] + 1));
}

// Block scan over 1024-element chunks (256 threads × 4 elems)
__global__ __launch_bounds__(256) void scan_block_kernel() {
    __shared__ int st[256];
    int base = blockIdx.x * SCHUNK;
    int tid = threadIdx.x;
    int v[4], pre[4];
    int s = 0;
#pragma unroll
    for (int i = 0; i < 4; i++) {
        int idx = base + tid * 4 + i;
        v[i] = (idx < NN) ? g_cin[idx] : 0;
        pre[i] = s;
        s += v[i];
    }
    st[tid] = s;
    __syncthreads();
#pragma unroll
    for (int off = 1; off < 256; off <<= 1) {
        int x = (tid >= off) ? st[tid - off] : 0;
        __syncthreads();
        st[tid] += x;
        __syncthreads();
    }
    int excl = st[tid] - s;
#pragma unroll
    for (int i = 0; i < 4; i++) {
        int idx = base + tid * 4 + i;
        if (idx < NN) g_off[idx] = excl + pre[i];
    }
    if (tid == 255) g_bsum[blockIdx.x] = st[255];
}

__global__ void scan_top_kernel() {
    if (threadIdx.x == 0 && blockIdx.x == 0) {
        int run = 0;
        for (int b = 0; b < NBLK_SCAN; b++) {
            int t = g_bsum[b];
            g_bsumex[b] = run;
            run += t;
        }
    }
}

__global__ void fill_kernel(const int* __restrict__ src, const int* __restrict__ dst) {
    int e = blockIdx.x * blockDim.x + threadIdx.x;
    if (e >= NE) return;
    int c = dst[e];
    int pos = g_off[c] + g_bsumex[c >> 10] + atomicAdd(&g_fill[c], 1);
    g_adj[pos] = src[e];
}

// ---------------------------------------------------------------------------
// Normalized CSR gather aggregation (pre-GEMM form):
//   y[c] = dinv[c] * ( dinv[c]*in[c] + sum_{r in in(c)} dinv[r]*in[r] )
// One warp per node; VPL float4 slots per lane (VPL=1 -> D=128, VPL=2 -> D=256).
// Output uses streaming stores to avoid evicting the gather working set from L2.
template<int VPL, int UN>
__global__ __launch_bounds__(256) void agg_kernel(
    const float* __restrict__ in, float* __restrict__ outp)
{
    int node = (blockIdx.x * blockDim.x + threadIdx.x) >> 5;
    int lane = threadIdx.x & 31;
    if (node >= NN) return;

    const float4* in4 = reinterpret_cast<const float4*>(in);
    size_t rb = (size_t)node * (VPL * 32);
    float dc = g_dinv[node];

    float4 acc[VPL];
#pragma unroll
    for (int v = 0; v < VPL; v++) {
        float4 s = in4[rb + v * 32 + lane];
        acc[v] = make_float4(s.x * dc, s.y * dc, s.z * dc, s.w * dc);
    }

    int start = g_off[node] + g_bsumex[node >> 10];
    int cnt = g_cin[node];

    int j = 0;
    for (; j + UN <= cnt; j += UN) {
        int rr[UN]; float ww[UN];
#pragma unroll
        for (int u = 0; u < UN; u++) rr[u] = g_adj[start + j + u];
#pragma unroll
        for (int u = 0; u < UN; u++) ww[u] = g_dinv[rr[u]];
#pragma unroll
        for (int u = 0; u < UN; u++) {
            size_t nb = (size_t)rr[u] * (VPL * 32);
#pragma unroll
            for (int v = 0; v < VPL; v++) {
                float4 x = in4[nb + v * 32 + lane];
                acc[v].x = fmaf(x.x, ww[u], acc[v].x);
                acc[v].y = fmaf(x.y, ww[u], acc[v].y);
                acc[v].z = fmaf(x.z, ww[u], acc[v].z);
                acc[v].w = fmaf(x.w, ww[u], acc[v].w);
            }
        }
    }
    for (; j < cnt; j++) {
        int r0 = g_adj[start + j];
        float w0 = g_dinv[r0];
        size_t nb = (size_t)r0 * (VPL * 32);
#pragma unroll
        for (int v = 0; v < VPL; v++) {
            float4 x = in4[nb + v * 32 + lane];
            acc[v].x = fmaf(x.x, w0, acc[v].x);
            acc[v].y = fmaf(x.y, w0, acc[v].y);
            acc[v].z = fmaf(x.z, w0, acc[v].z);
            acc[v].w = fmaf(x.w, w0, acc[v].w);
        }
    }

#pragma unroll
    for (int v = 0; v < VPL; v++) {
        float4 o = make_float4(acc[v].x * dc, acc[v].y * dc,
                               acc[v].z * dc, acc[v].w * dc);
        float* addr = outp + (rb + v * 32 + lane) * 4;
        asm volatile("st.global.cs.v4.f32 [%0], {%1, %2, %3, %4};"
                     :: "l"(addr), "f"(o.x), "f"(o.y), "f"(o.z), "f"(o.w)
                     : "memory");
    }
}

// ---------------------------------------------------------------------------
// Tensor-core tf32 GEMM with fused bias+ReLU epilogue:
//   C[m,:] = relu(A[m,:] @ B + bias)
// CTA tile 128x128, BK=16, 8 warps (warp tile 64x32), mma.m16n8k8.tf32,
// cp.async double-buffered shared memory.
#define TBM 128
#define TBN 128
#define TBK 16
#define APAD 20    // floats per A smem row (conflict-free for frag loads)
#define BPAD 136   // floats per B smem row

__device__ __forceinline__ uint32_t f2tf32(float f) {
    uint32_t u;
    asm("cvt.rna.tf32.f32 %0, %1;" : "=r"(u) : "f"(f));
    return u;
}

__device__ __forceinline__ void mma_tf32(float* d,
    uint32_t a0, uint32_t a1, uint32_t a2, uint32_t a3,
    uint32_t b0, uint32_t b1)
{
    asm volatile("mma.sync.aligned.m16n8k8.row.col.f32.tf32.tf32.f32 "
        "{%0,%1,%2,%3}, {%4,%5,%6,%7}, {%8,%9}, {%0,%1,%2,%3};\n"
        : "+f"(d[0]), "+f"(d[1]), "+f"(d[2]), "+f"(d[3])
        : "r"(a0), "r"(a1), "r"(a2), "r"(a3), "r"(b0), "r"(b1));
}

__global__ __launch_bounds__(256) void gemm_tc_kernel(
    const float* __restrict__ A, const float* __restrict__ B,
    const float* __restrict__ bias, float* __restrict__ C,
    int M, int K, int N)
{
    __shared__ float As[2][TBM * APAD];
    __shared__ float Bs[2][TBK * BPAD];

    int tid  = threadIdx.x;
    int lane = tid & 31;
    int warp = tid >> 5;
    int warpM = warp & 1;    // 0..1  (64 rows each)
    int warpN = warp >> 1;   // 0..3  (32 cols each)
    int rowBase = blockIdx.y * TBM;
    int colBase = blockIdx.x * TBN;

    // loader mapping
    int aRow = tid >> 2;          // 0..63
    int aC4  = (tid & 3) * 4;     // 0,4,8,12
    int bRow = tid >> 5;          // 0..7
    int bC4  = (tid & 31) * 4;    // 0..124

    float acc[4][4][4];
#pragma unroll
    for (int mt = 0; mt < 4; mt++)
#pragma unroll
        for (int nt = 0; nt < 4; nt++)
#pragma unroll
            for (int i = 0; i < 4; i++) acc[mt][nt][i] = 0.0f;

    auto load_tiles = [&](int s, int k0) {
#pragma unroll
        for (int i = 0; i < 2; i++) {
            int r = aRow + i * 64;
            int gr = rowBase + r;
            const float* src = A + (size_t)(gr < M ? gr : 0) * K + k0 + aC4;
            uint32_t dst = (uint32_t)__cvta_generic_to_shared(&As[s][r * APAD + aC4]);
            int sz = (gr < M) ? 16 : 0;
            asm volatile("cp.async.cg.shared.global [%0], [%1], 16, %2;\n"
                         :: "r"(dst), "l"(src), "r"(sz));
        }
#pragma unroll
        for (int i = 0; i < 2; i++) {
            int r = bRow + i * 8;
            const float* src = B + (size_t)(k0 + r) * N + colBase + bC4;
            uint32_t dst = (uint32_t)__cvta_generic_to_shared(&Bs[s][r * BPAD + bC4]);
            asm volatile("cp.async.cg.shared.global [%0], [%1], 16;\n"
                         :: "r"(dst), "l"(src));
        }
    };

    auto compute = [&](int s) {
        int r = lane >> 2;
        int c = lane & 3;
#pragma unroll
        for (int kg = 0; kg < 2; kg++) {
            uint32_t af[4][4], bf[4][2];
#pragma unroll
            for (int mt = 0; mt < 4; mt++) {
                int mb = warpM * 64 + mt * 16;
                float x0 = As[s][(mb + r)     * APAD + kg * 8 + c];
                float x1 = As[s][(mb + r + 8) * APAD + kg * 8 + c];
                float x2 = As[s][(mb + r)     * APAD + kg * 8 + c + 4];
                float x3 = As[s][(mb + r + 8) * APAD + kg * 8 + c + 4];
                af[mt][0] = f2tf32(x0); af[mt][1] = f2tf32(x1);
                af[mt][2] = f2tf32(x2); af[mt][3] = f2tf32(x3);
            }
#pragma unroll
            for (int nt = 0; nt < 4; nt++) {
                int nb = warpN * 32 + nt * 8;
                float y0 = Bs[s][(kg * 8 + c)     * BPAD + nb + r];
                float y1 = Bs[s][(kg * 8 + c + 4) * BPAD + nb + r];
                bf[nt][0] = f2tf32(y0); bf[nt][1] = f2tf32(y1);
            }
#pragma unroll
            for (int mt = 0; mt < 4; mt++)
#pragma unroll
                for (int nt = 0; nt < 4; nt++)
                    mma_tf32(acc[mt][nt],
                             af[mt][0], af[mt][1], af[mt][2], af[mt][3],
                             bf[nt][0], bf[nt][1]);
        }
    };

    load_tiles(0, 0);
    asm volatile("cp.async.commit_group;\n");
    int buf = 0;
    for (int k0 = TBK; k0 < K; k0 += TBK) {
        load_tiles(buf ^ 1, k0);
        asm volatile("cp.async.commit_group;\n");
        asm volatile("cp.async.wait_group 1;\n");
        __syncthreads();
        compute(buf);
        __syncthreads();
        buf ^= 1;
    }
    asm volatile("cp.async.wait_group 0;\n");
    __syncthreads();
    compute(buf);

    // Epilogue: relu(acc + bias)
    int r = lane >> 2;
    int c = lane & 3;
    float2 bb[4];
#pragma unroll
    for (int nt = 0; nt < 4; nt++) {
        int gcol = colBase + warpN * 32 + nt * 8 + c * 2;
        bb[nt] = *reinterpret_cast<const float2*>(bias + gcol);
    }
#pragma unroll
    for (int mt = 0; mt < 4; mt++) {
        int grow0 = rowBase + warpM * 64 + mt * 16 + r;
        int grow1 = grow0 + 8;
#pragma unroll
        for (int nt = 0; nt < 4; nt++) {
            int gcol = colBase + warpN * 32 + nt * 8 + c * 2;
            if (grow0 < M) {
                float2 v = make_float2(fmaxf(acc[mt][nt][0] + bb[nt].x, 0.f),
                                       fmaxf(acc[mt][nt][1] + bb[nt].y, 0.f));
                *reinterpret_cast<float2*>(C + (size_t)grow0 * N + gcol) = v;
            }
            if (grow1 < M) {
                float2 v = make_float2(fmaxf(acc[mt][nt][2] + bb[nt].x, 0.f),
                                       fmaxf(acc[mt][nt][3] + bb[nt].y, 0.f));
                *reinterpret_cast<float2*>(C + (size_t)grow1 * N + gcol) = v;
            }
        }
    }
}

// ---------------------------------------------------------------------------
__global__ void zero_out_kernel(float* __restrict__ out) {
    int idx = blockIdx.x * blockDim.x + threadIdx.x;
    if (idx < NG * DH) out[idx] = 0.0f;
}

#define POOL_CHUNK 512
__global__ __launch_bounds__(256) void pool_kernel(
    const int* __restrict__ batch, float* __restrict__ out)
{
    __shared__ int sb[POOL_CHUNK];
    int start = blockIdx.x * POOL_CHUNK;
    int end = min(start + POOL_CHUNK, NN);
    int cnt = end - start;
    for (int i = threadIdx.x; i < cnt; i += blockDim.x) sb[i] = batch[start + i];
    __syncthreads();

    int d = threadIdx.x;
    int curg = sb[0];
    float acc = 0.0f;
    int run = 0;
    for (int n = 0; n < cnt; n++) {
        int g = sb[n];
        if (g != curg) {
            atomicAdd(&out[curg * DH + d], acc);
            if (d == 0) atomicAdd(&g_cnt[curg], run);
            acc = 0.0f; run = 0; curg = g;
        }
        acc += g_a[(size_t)(start + n) * DH + d];
        run++;
    }
    atomicAdd(&out[curg * DH + d], acc);
    if (d == 0) atomicAdd(&g_cnt[curg], run);
}

__global__ void divide_kernel(float* __restrict__ out) {
    int idx = blockIdx.x * blockDim.x + threadIdx.x;
    if (idx >= NG * DH) return;
    int g = idx >> 8;
    float c = (float)g_cnt[g];
    out[idx] = out[idx] / fmaxf(c, 1.0f);
}

// ---------------------------------------------------------------------------
extern "C" void kernel_launch(void* const* d_in, const int* in_sizes, int n_in,
                              void* d_out, int out_size)
{
    const float* x    = (const float*)d_in[0];   // [NN, 128]
    const int*   ei   = (const int*)  d_in[1];   // [2, NE]
    const int*   batch= (const int*)  d_in[2];   // [NN]
    const float* W1   = (const float*)d_in[3];   // [128, 256]
    const float* b1   = (const float*)d_in[4];   // [256]
    const float* W2   = (const float*)d_in[5];   // [256, 256]
    const float* b2   = (const float*)d_in[6];   // [256]
    float* out = (float*)d_out;                  // [64, 256]

    const int* src = ei;        // edge_index[0] = source
    const int* dst = ei + NE;   // edge_index[1] = target

    float* d_h; cudaGetSymbolAddress((void**)&d_h, g_h);
    float* d_a; cudaGetSymbolAddress((void**)&d_a, g_a);

    // ---- CSR build + normalization ----
    zero_kernel<<<(NN + 255) / 256, 256>>>();
    hist_kernel<<<(NE + 255) / 256, 256>>>(dst);
    dinv_kernel<<<(NN + 255) / 256, 256>>>();
    scan_block_kernel<<<NBLK_SCAN, 256>>>();
    scan_top_kernel<<<1, 32>>>();
    fill_kernel<<<(NE + 255) / 256, 256>>>(src, dst);

    dim3 gemmBlock(256);
    dim3 gemmGrid(DH / TBN, (NN + TBM - 1) / TBM);   // (2, 782)
    int aggGrid = (NN * 32 + 255) / 256;

    // ---- Layer 1: aggregate(x) in 128-dim, then GEMM+bias+relu ----
    agg_kernel<1, 4><<<aggGrid, 256>>>(x, d_h);               // y1 = A_norm x   [NN,128]
    gemm_tc_kernel<<<gemmGrid, gemmBlock>>>(d_h, W1, b1, d_a, NN, DIN, DH);  // a1

    // ---- Layer 2: aggregate(a1) in 256-dim, then GEMM+bias+relu ----
    agg_kernel<2, 2><<<aggGrid, 256>>>(d_a, d_h);             // y2 = A_norm a1  [NN,256]
    gemm_tc_kernel<<<gemmGrid, gemmBlock>>>(d_h, W2, b2, d_a, NN, DH, DH);   // a2

    // ---- Global mean pool ----
    zero_out_kernel<<<(NG * DH + 255) / 256, 256>>>(out);
    pool_kernel<<<(NN + POOL_CHUNK - 1) / POOL_CHUNK, 256>>>(batch, out);
    divide_kernel<<<(NG * DH + 255) / 256, 256>>>(out);
}

// round 6
// speedup vs baseline: 4.6682x; 1.7729x over previous
#include <cuda_runtime.h>
#include <cuda_fp16.h>
#include <cstdint>

// Problem constants (fixed by the dataset)
constexpr int NN   = 100000;   // nodes
constexpr int NE   = 1600000;  // edges
constexpr int NG   = 64;       // graphs
constexpr int DIN  = 128;
constexpr int DH   = 256;      // hidden == out dim

constexpr int SCHUNK = 1024;
constexpr int NBLK_SCAN = (NN + SCHUNK - 1) / SCHUNK;  // 98

// Scratch (device globals — no allocations allowed)
__device__ __align__(16) float  g_dinv[NN];
__device__ __align__(16) __half g_h [(size_t)NN * DH];   // agg outputs y1/y2 (fp16)
__device__ __align__(16) float  g_a [(size_t)NN * DH];   // a1 (as half, low part) / a2 (fp32)
__device__ __align__(16) __half g_wt1[DH * DIN];         // W1^T fp16 [256][128]
__device__ __align__(16) __half g_wt2[DH * DH];          // W2^T fp16 [256][256]
__device__ int g_cin [NN];
__device__ int g_off [NN];
__device__ int g_bsum[NBLK_SCAN];
__device__ int g_bsumex[NBLK_SCAN];
__device__ int g_fill[NN];
__device__ int g_adj [NE];
__device__ int g_cnt [NG];

// ---------------------------------------------------------------------------
__global__ void zero_kernel() {
    int i = blockIdx.x * blockDim.x + threadIdx.x;
    if (i < NN) { g_cin[i] = 0; g_fill[i] = 0; }
    if (i < NG) g_cnt[i] = 0;
}

__global__ void hist_kernel(const int* __restrict__ dst) {
    int e = blockIdx.x * blockDim.x + threadIdx.x;
    if (e < NE) atomicAdd(&g_cin[dst[e]], 1);
}

__global__ void dinv_kernel() {
    int i = blockIdx.x * blockDim.x + threadIdx.x;
    if (i < NN) g_dinv[i] = rsqrtf((float)(g_cin[i] + 1));
}

__global__ __launch_bounds__(256) void scan_block_kernel() {
    __shared__ int st[256];
    int base = blockIdx.x * SCHUNK;
    int tid = threadIdx.x;
    int v[4], pre[4];
    int s = 0;
#pragma unroll
    for (int i = 0; i < 4; i++) {
        int idx = base + tid * 4 + i;
        v[i] = (idx < NN) ? g_cin[idx] : 0;
        pre[i] = s;
        s += v[i];
    }
    st[tid] = s;
    __syncthreads();
#pragma unroll
    for (int off = 1; off < 256; off <<= 1) {
        int x = (tid >= off) ? st[tid - off] : 0;
        __syncthreads();
        st[tid] += x;
        __syncthreads();
    }
    int excl = st[tid] - s;
#pragma unroll
    for (int i = 0; i < 4; i++) {
        int idx = base + tid * 4 + i;
        if (idx < NN) g_off[idx] = excl + pre[i];
    }
    if (tid == 255) g_bsum[blockIdx.x] = st[255];
}

__global__ void scan_top_kernel() {
    if (threadIdx.x == 0 && blockIdx.x == 0) {
        int run = 0;
        for (int b = 0; b < NBLK_SCAN; b++) {
            int t = g_bsum[b];
            g_bsumex[b] = run;
            run += t;
        }
    }
}

__global__ void fill_kernel(const int* __restrict__ src, const int* __restrict__ dst) {
    int e = blockIdx.x * blockDim.x + threadIdx.x;
    if (e >= NE) return;
    int c = dst[e];
    int pos = g_off[c] + g_bsumex[c >> 10] + atomicAdd(&g_fill[c], 1);
    g_adj[pos] = src[e];
}

// ---------------------------------------------------------------------------
// Weight transpose + fp32->fp16: Wt[n*K + k] = (half)W[k*256 + n]
__global__ void transpose_kernel(const float* __restrict__ W, __half* __restrict__ Wt, int K) {
    __shared__ float t[32][33];
    int kb = blockIdx.x * 32, nb = blockIdx.y * 32;
    int x = threadIdx.x, y = threadIdx.y;  // block (32, 8)
#pragma unroll
    for (int i = 0; i < 32; i += 8)
        t[y + i][x] = W[(size_t)(kb + y + i) * DH + nb + x];
    __syncthreads();
#pragma unroll
    for (int i = 0; i < 32; i += 8)
        Wt[(size_t)(nb + y + i) * K + kb + x] = __float2half(t[x][y + i]);
}

// ---------------------------------------------------------------------------
// Streaming store helpers
__device__ __forceinline__ void st_cs_v2(void* addr, uint32_t a, uint32_t b) {
    asm volatile("st.global.cs.v2.b32 [%0], {%1, %2};" :: "l"(addr), "r"(a), "r"(b) : "memory");
}
__device__ __forceinline__ void st_cs_v4(void* addr, uint4 v) {
    asm volatile("st.global.cs.v4.b32 [%0], {%1, %2, %3, %4};"
                 :: "l"(addr), "r"(v.x), "r"(v.y), "r"(v.z), "r"(v.w) : "memory");
}

// ---------------------------------------------------------------------------
// Layer-1 aggregation: fp32 input (x, D=128), fp16 output.
//   y[c] = dinv[c] * ( dinv[c]*x[c] + sum_r dinv[r]*x[r] )
// 16 lanes per node; each lane owns 2 float4 slots (8 dims).
__global__ __launch_bounds__(256) void agg_f32_kernel(
    const float* __restrict__ in, __half* __restrict__ outp)
{
    int gtid = blockIdx.x * blockDim.x + threadIdx.x;
    int node = gtid >> 4;
    int lane = threadIdx.x & 15;
    if (node >= NN) return;

    const float4* in4 = reinterpret_cast<const float4*>(in);
    size_t rb = (size_t)node * 32;           // 32 float4 per row
    float dc = g_dinv[node];

    float4 acc[2];
#pragma unroll
    for (int v = 0; v < 2; v++) {
        float4 s = in4[rb + v * 16 + lane];
        acc[v] = make_float4(s.x * dc, s.y * dc, s.z * dc, s.w * dc);
    }

    int start = g_off[node] + g_bsumex[node >> 10];
    int cnt = g_cin[node];
    int j = 0;
    for (; j + 4 <= cnt; j += 4) {
        int rr[4]; float ww[4];
#pragma unroll
        for (int u = 0; u < 4; u++) rr[u] = g_adj[start + j + u];
#pragma unroll
        for (int u = 0; u < 4; u++) ww[u] = g_dinv[rr[u]];
#pragma unroll
        for (int u = 0; u < 4; u++) {
            size_t nb = (size_t)rr[u] * 32;
#pragma unroll
            for (int v = 0; v < 2; v++) {
                float4 x = in4[nb + v * 16 + lane];
                acc[v].x = fmaf(x.x, ww[u], acc[v].x);
                acc[v].y = fmaf(x.y, ww[u], acc[v].y);
                acc[v].z = fmaf(x.z, ww[u], acc[v].z);
                acc[v].w = fmaf(x.w, ww[u], acc[v].w);
            }
        }
    }
    for (; j < cnt; j++) {
        int r0 = g_adj[start + j];
        float w0 = g_dinv[r0];
        size_t nb = (size_t)r0 * 32;
#pragma unroll
        for (int v = 0; v < 2; v++) {
            float4 x = in4[nb + v * 16 + lane];
            acc[v].x = fmaf(x.x, w0, acc[v].x);
            acc[v].y = fmaf(x.y, w0, acc[v].y);
            acc[v].z = fmaf(x.z, w0, acc[v].z);
            acc[v].w = fmaf(x.w, w0, acc[v].w);
        }
    }

#pragma unroll
    for (int v = 0; v < 2; v++) {
        __half2 h0 = __floats2half2_rn(acc[v].x * dc, acc[v].y * dc);
        __half2 h1 = __floats2half2_rn(acc[v].z * dc, acc[v].w * dc);
        // 4 halves = 8 bytes at half-index (rb + v*16 + lane)*4
        __half* addr = outp + (rb + (size_t)v * 16 + lane) * 4;
        st_cs_v2(addr, *reinterpret_cast<uint32_t*>(&h0), *reinterpret_cast<uint32_t*>(&h1));
    }
}

// ---------------------------------------------------------------------------
// Layer-2 aggregation: fp16 input (a1, D=256), fp32 accumulate, fp16 output.
// 16 lanes per node; each lane owns 2 uint4 slots (16 halves = 16 dims).
__global__ __launch_bounds__(256) void agg_f16_kernel(
    const __half* __restrict__ in, __half* __restrict__ outp)
{
    int gtid = blockIdx.x * blockDim.x + threadIdx.x;
    int node = gtid >> 4;
    int lane = threadIdx.x & 15;
    if (node >= NN) return;

    const uint4* in8 = reinterpret_cast<const uint4*>(in);  // 8 halves per uint4
    size_t rb = (size_t)node * 32;            // 32 uint4 per row
    float dc = g_dinv[node];

    float2 acc[2][4];                          // [slot][half2 pair]
#pragma unroll
    for (int v = 0; v < 2; v++) {
        uint4 s = in8[rb + v * 16 + lane];
        const __half2* h = reinterpret_cast<const __half2*>(&s);
#pragma unroll
        for (int p = 0; p < 4; p++) {
            float2 f = __half22float2(h[p]);
            acc[v][p] = make_float2(f.x * dc, f.y * dc);
        }
    }

    int start = g_off[node] + g_bsumex[node >> 10];
    int cnt = g_cin[node];
    int j = 0;
    for (; j + 4 <= cnt; j += 4) {
        int rr[4]; float ww[4];
#pragma unroll
        for (int u = 0; u < 4; u++) rr[u] = g_adj[start + j + u];
#pragma unroll
        for (int u = 0; u < 4; u++) ww[u] = g_dinv[rr[u]];
#pragma unroll
        for (int u = 0; u < 4; u++) {
            size_t nb = (size_t)rr[u] * 32;
#pragma unroll
            for (int v = 0; v < 2; v++) {
                uint4 s = in8[nb + v * 16 + lane];
                const __half2* h = reinterpret_cast<const __half2*>(&s);
#pragma unroll
                for (int p = 0; p < 4; p++) {
                    float2 f = __half22float2(h[p]);
                    acc[v][p].x = fmaf(f.x, ww[u], acc[v][p].x);
                    acc[v][p].y = fmaf(f.y, ww[u], acc[v][p].y);
                }
            }
        }
    }
    for (; j < cnt; j++) {
        int r0 = g_adj[start + j];
        float w0 = g_dinv[r0];
        size_t nb = (size_t)r0 * 32;
#pragma unroll
        for (int v = 0; v < 2; v++) {
            uint4 s = in8[nb + v * 16 + lane];
            const __half2* h = reinterpret_cast<const __half2*>(&s);
#pragma unroll
            for (int p = 0; p < 4; p++) {
                float2 f = __half22float2(h[p]);
                acc[v][p].x = fmaf(f.x, w0, acc[v][p].x);
                acc[v][p].y = fmaf(f.y, w0, acc[v][p].y);
            }
        }
    }

#pragma unroll
    for (int v = 0; v < 2; v++) {
        uint4 o;
        uint32_t* ow = &o.x;
#pragma unroll
        for (int p = 0; p < 4; p++) {
            __half2 h = __floats2half2_rn(acc[v][p].x * dc, acc[v][p].y * dc);
            ow[p] = *reinterpret_cast<uint32_t*>(&h);
        }
        __half* addr = outp + (rb + (size_t)v * 16 + lane) * 8;
        st_cs_v4(addr, o);
    }
}

// ---------------------------------------------------------------------------
// fp16 tensor-core GEMM (legacy mma.sync m16n8k16, fp32 accumulate):
//   C[m, colBase:+128] = relu(A[m,:K] @ Bt^T + bias)
// A: [M,K] half row-major.  Bt: [256,K] half row-major (pre-transposed weight).
// CTA tile 128x128, BK=32, 8 warps (warp tile 64x32), double-buffered cp.async.
#define HPAD 40   // halves per padded smem row (80 bytes; conflict-free, see analysis)

__device__ __forceinline__ void mma_f16(float* d, const uint32_t* a, const uint32_t* b) {
    asm volatile("mma.sync.aligned.m16n8k16.row.col.f32.f16.f16.f32 "
        "{%0,%1,%2,%3}, {%4,%5,%6,%7}, {%8,%9}, {%0,%1,%2,%3};\n"
        : "+f"(d[0]), "+f"(d[1]), "+f"(d[2]), "+f"(d[3])
        : "r"(a[0]), "r"(a[1]), "r"(a[2]), "r"(a[3]), "r"(b[0]), "r"(b[1]));
}

template<bool OUT_HALF>
__global__ __launch_bounds__(256) void gemm_f16_kernel(
    const __half* __restrict__ A, const __half* __restrict__ Bt,
    const float* __restrict__ bias, void* __restrict__ Cv,
    int M, int K)
{
    __shared__ __half As[2][128 * HPAD];
    __shared__ __half Bs[2][128 * HPAD];

    int tid  = threadIdx.x;
    int lane = tid & 31;
    int warp = tid >> 5;
    int warpM = warp & 1;    // 64 rows each
    int warpN = warp >> 1;   // 32 cols each
    int rowBase = blockIdx.y * 128;
    int colBase = blockIdx.x * 128;

    float acc[4][4][4];
#pragma unroll
    for (int mt = 0; mt < 4; mt++)
#pragma unroll
        for (int nt = 0; nt < 4; nt++)
#pragma unroll
            for (int i = 0; i < 4; i++) acc[mt][nt][i] = 0.0f;

    // loaders: tile = 128 rows x 32 halves = 512 16B-chunks; 2 per thread
    auto load_tiles = [&](int s, int k0) {
#pragma unroll
        for (int i = 0; i < 2; i++) {
            int idx = tid + i * 256;      // 0..511
            int row = idx >> 2;           // 0..127
            int c   = idx & 3;            // 16B chunk in row (8 halves)
            // A
            int gr = rowBase + row;
            const __half* srcA = A + (size_t)(gr < M ? gr : 0) * K + k0 + c * 8;
            uint32_t dstA = (uint32_t)__cvta_generic_to_shared(&As[s][row * HPAD + c * 8]);
            int sz = (gr < M) ? 16 : 0;
            asm volatile("cp.async.cg.shared.global [%0], [%1], 16, %2;\n"
                         :: "r"(dstA), "l"(srcA), "r"(sz));
            // B
            const __half* srcB = Bt + (size_t)(colBase + row) * K + k0 + c * 8;
            uint32_t dstB = (uint32_t)__cvta_generic_to_shared(&Bs[s][row * HPAD + c * 8]);
            asm volatile("cp.async.cg.shared.global [%0], [%1], 16;\n"
                         :: "r"(dstB), "l"(srcB));
        }
    };

    int r = lane >> 2;        // 0..7
    int kq = (lane & 3) * 2;  // 0,2,4,6

    auto compute = [&](int s) {
#pragma unroll
        for (int kg = 0; kg < 2; kg++) {    // two k16 groups in BK=32
            int kb = kg * 16;
            uint32_t af[4][4], bf[4][2];
#pragma unroll
            for (int mt = 0; mt < 4; mt++) {
                int mb = warpM * 64 + mt * 16;
                const __half* base = &As[s][0];
                af[mt][0] = *reinterpret_cast<const uint32_t*>(base + (mb + r)     * HPAD + kb + kq);
                af[mt][1] = *reinterpret_cast<const uint32_t*>(base + (mb + r + 8) * HPAD + kb + kq);
                af[mt][2] = *reinterpret_cast<const uint32_t*>(base + (mb + r)     * HPAD + kb + kq + 8);
                af[mt][3] = *reinterpret_cast<const uint32_t*>(base + (mb + r + 8) * HPAD + kb + kq + 8);
            }
#pragma unroll
            for (int nt = 0; nt < 4; nt++) {
                int nb = warpN * 32 + nt * 8;
                const __half* base = &Bs[s][0];
                bf[nt][0] = *reinterpret_cast<const uint32_t*>(base + (nb + r) * HPAD + kb + kq);
                bf[nt][1] = *reinterpret_cast<const uint32_t*>(base + (nb + r) * HPAD + kb + kq + 8);
            }
#pragma unroll
            for (int mt = 0; mt < 4; mt++)
#pragma unroll
                for (int nt = 0; nt < 4; nt++)
                    mma_f16(acc[mt][nt], af[mt], bf[nt]);
        }
    };

    load_tiles(0, 0);
    asm volatile("cp.async.commit_group;\n");
    int buf = 0;
    for (int k0 = 32; k0 < K; k0 += 32) {
        load_tiles(buf ^ 1, k0);
        asm volatile("cp.async.commit_group;\n");
        asm volatile("cp.async.wait_group 1;\n");
        __syncthreads();
        compute(buf);
        __syncthreads();
        buf ^= 1;
    }
    asm volatile("cp.async.wait_group 0;\n");
    __syncthreads();
    compute(buf);

    // Epilogue: relu(acc + bias); fp16 or fp32 output
    int c2 = (lane & 3) * 2;
    float2 bb[4];
#pragma unroll
    for (int nt = 0; nt < 4; nt++) {
        int gcol = colBase + warpN * 32 + nt * 8 + c2;
        bb[nt] = *reinterpret_cast<const float2*>(bias + gcol);
    }
#pragma unroll
    for (int mt = 0; mt < 4; mt++) {
        int grow0 = rowBase + warpM * 64 + mt * 16 + r;
        int grow1 = grow0 + 8;
#pragma unroll
        for (int nt = 0; nt < 4; nt++) {
            int gcol = colBase + warpN * 32 + nt * 8 + c2;
            float v00 = fmaxf(acc[mt][nt][0] + bb[nt].x, 0.f);
            float v01 = fmaxf(acc[mt][nt][1] + bb[nt].y, 0.f);
            float v10 = fmaxf(acc[mt][nt][2] + bb[nt].x, 0.f);
            float v11 = fmaxf(acc[mt][nt][3] + bb[nt].y, 0.f);
            if (OUT_HALF) {
                __half* C = (__half*)Cv;
                if (grow0 < M) {
                    __half2 h = __floats2half2_rn(v00, v01);
                    *reinterpret_cast<uint32_t*>(C + (size_t)grow0 * DH + gcol) =
                        *reinterpret_cast<uint32_t*>(&h);
                }
                if (grow1 < M) {
                    __half2 h = __floats2half2_rn(v10, v11);
                    *reinterpret_cast<uint32_t*>(C + (size_t)grow1 * DH + gcol) =
                        *reinterpret_cast<uint32_t*>(&h);
                }
            } else {
                float* C = (float*)Cv;
                if (grow0 < M)
                    *reinterpret_cast<float2*>(C + (size_t)grow0 * DH + gcol) = make_float2(v00, v01);
                if (grow1 < M)
                    *reinterpret_cast<float2*>(C + (size_t)grow1 * DH + gcol) = make_float2(v10, v11);
            }
        }
    }
}

// ---------------------------------------------------------------------------
__global__ void zero_out_kernel(float* __restrict__ out) {
    int idx = blockIdx.x * blockDim.x + threadIdx.x;
    if (idx < NG * DH) out[idx] = 0.0f;
}

#define POOL_CHUNK 128
__global__ __launch_bounds__(256) void pool_kernel(
    const int* __restrict__ batch, float* __restrict__ out)
{
    __shared__ int sb[POOL_CHUNK];
    int start = blockIdx.x * POOL_CHUNK;
    int end = min(start + POOL_CHUNK, NN);
    int cnt = end - start;
    for (int i = threadIdx.x; i < cnt; i += blockDim.x) sb[i] = batch[start + i];
    __syncthreads();

    int d = threadIdx.x;
    int curg = sb[0];
    float acc = 0.0f;
    int run = 0;
    for (int n = 0; n < cnt; n++) {
        int g = sb[n];
        if (g != curg) {
            atomicAdd(&out[curg * DH + d], acc);
            if (d == 0) atomicAdd(&g_cnt[curg], run);
            acc = 0.0f; run = 0; curg = g;
        }
        acc += g_a[(size_t)(start + n) * DH + d];
        run++;
    }
    atomicAdd(&out[curg * DH + d], acc);
    if (d == 0) atomicAdd(&g_cnt[curg], run);
}

__global__ void divide_kernel(float* __restrict__ out) {
    int idx = blockIdx.x * blockDim.x + threadIdx.x;
    if (idx >= NG * DH) return;
    int g = idx >> 8;
    float c = (float)g_cnt[g];
    out[idx] = out[idx] / fmaxf(c, 1.0f);
}

// ---------------------------------------------------------------------------
extern "C" void kernel_launch(void* const* d_in, const int* in_sizes, int n_in,
                              void* d_out, int out_size)
{
    const float* x    = (const float*)d_in[0];   // [NN, 128]
    const int*   ei   = (const int*)  d_in[1];   // [2, NE]
    const int*   batch= (const int*)  d_in[2];   // [NN]
    const float* W1   = (const float*)d_in[3];   // [128, 256]
    const float* b1   = (const float*)d_in[4];   // [256]
    const float* W2   = (const float*)d_in[5];   // [256, 256]
    const float* b2   = (const float*)d_in[6];   // [256]
    float* out = (float*)d_out;                  // [64, 256]

    const int* src = ei;
    const int* dst = ei + NE;

    __half* d_h;   cudaGetSymbolAddress((void**)&d_h, g_h);
    float*  d_a;   cudaGetSymbolAddress((void**)&d_a, g_a);
    __half* d_a_h = (__half*)d_a;                 // a1 stored as half in g_a storage
    __half* d_wt1; cudaGetSymbolAddress((void**)&d_wt1, g_wt1);
    __half* d_wt2; cudaGetSymbolAddress((void**)&d_wt2, g_wt2);

    // ---- weight transposes + fp16 convert ----
    transpose_kernel<<<dim3(DIN / 32, DH / 32), dim3(32, 8)>>>(W1, d_wt1, DIN);
    transpose_kernel<<<dim3(DH / 32, DH / 32), dim3(32, 8)>>>(W2, d_wt2, DH);

    // ---- CSR build + normalization ----
    zero_kernel<<<(NN + 255) / 256, 256>>>();
    hist_kernel<<<(NE + 255) / 256, 256>>>(dst);
    dinv_kernel<<<(NN + 255) / 256, 256>>>();
    scan_block_kernel<<<NBLK_SCAN, 256>>>();
    scan_top_kernel<<<1, 32>>>();
    fill_kernel<<<(NE + 255) / 256, 256>>>(src, dst);

    dim3 gemmGrid(2, (NN + 127) / 128);   // (2, 782)

    // ---- Layer 1: agg(x) fp32->fp16, GEMM fp16 -> a1 (fp16) ----
    agg_f32_kernel<<<(NN * 16 + 255) / 256, 256>>>(x, d_h);
    gemm_f16_kernel<true><<<gemmGrid, 256>>>(d_h, d_wt1, b1, d_a_h, NN, DIN);

    // ---- Layer 2: agg(a1) fp16->fp16, GEMM fp16 -> a2 (fp32) ----
    agg_f16_kernel<<<(NN * 16 + 255) / 256, 256>>>(d_a_h, d_h);
    gemm_f16_kernel<false><<<gemmGrid, 256>>>(d_h, d_wt2, b2, d_a, NN, DH);

    // ---- Global mean pool ----
    zero_out_kernel<<<(NG * DH + 255) / 256, 256>>>(out);
    pool_kernel<<<(NN + POOL_CHUNK - 1) / POOL_CHUNK, 256>>>(batch, out);
    divide_kernel<<<(NG * DH + 255) / 256, 256>>>(out);
}

// round 7
// speedup vs baseline: 5.3489x; 1.1458x over previous
#include <cuda_runtime.h>
#include <cuda_fp16.h>
#include <cstdint>

// Problem constants (fixed by the dataset)
constexpr int NN   = 100000;   // nodes
constexpr int NE   = 1600000;  // edges
constexpr int NG   = 64;       // graphs
constexpr int DIN  = 128;
constexpr int DH   = 256;      // hidden == out dim

constexpr int SCHUNK = 1024;
constexpr int NBLK_SCAN = (NN + SCHUNK - 1) / SCHUNK;  // 98

// Scratch (device globals — no allocations allowed)
__device__ __align__(16) float  g_dinv[NN];
__device__ __align__(16) __half g_x16[(size_t)NN * DIN]; // fp16 copy of x
__device__ __align__(16) __half g_h [(size_t)NN * DH];   // agg outputs y1/y2 (fp16)
__device__ __align__(16) __half g_a [(size_t)NN * DH];   // GEMM outputs a1/a2 (fp16)
__device__ __align__(16) __half g_wt1[DH * DIN];         // W1^T fp16 [256][128]
__device__ __align__(16) __half g_wt2[DH * DH];          // W2^T fp16 [256][256]
__device__ int g_cin [NN];
__device__ int g_off [NN];
__device__ int g_bsum[NBLK_SCAN];
__device__ int g_bsumex[NBLK_SCAN];
__device__ int g_fill[NN];
__device__ int g_adj [NE];
__device__ int g_cnt [NG];

// ---------------------------------------------------------------------------
__global__ void zero_kernel() {
    int i = blockIdx.x * blockDim.x + threadIdx.x;
    if (i < NN) { g_cin[i] = 0; g_fill[i] = 0; }
    if (i < NG) g_cnt[i] = 0;
}

__global__ void hist_kernel(const int* __restrict__ dst) {
    int e = blockIdx.x * blockDim.x + threadIdx.x;
    if (e < NE) atomicAdd(&g_cin[dst[e]], 1);
}

// Block scan over 1024-element chunks + fused dinv computation
__global__ __launch_bounds__(256) void scan_block_kernel() {
    __shared__ int st[256];
    int base = blockIdx.x * SCHUNK;
    int tid = threadIdx.x;
    int v[4], pre[4];
    int s = 0;
#pragma unroll
    for (int i = 0; i < 4; i++) {
        int idx = base + tid * 4 + i;
        v[i] = (idx < NN) ? g_cin[idx] : 0;
        if (idx < NN) g_dinv[idx] = rsqrtf((float)(v[i] + 1));
        pre[i] = s;
        s += v[i];
    }
    st[tid] = s;
    __syncthreads();
#pragma unroll
    for (int off = 1; off < 256; off <<= 1) {
        int x = (tid >= off) ? st[tid - off] : 0;
        __syncthreads();
        st[tid] += x;
        __syncthreads();
    }
    int excl = st[tid] - s;
#pragma unroll
    for (int i = 0; i < 4; i++) {
        int idx = base + tid * 4 + i;
        if (idx < NN) g_off[idx] = excl + pre[i];
    }
    if (tid == 255) g_bsum[blockIdx.x] = st[255];
}

// Parallel exclusive scan of the 98 chunk totals (one block, 128 threads)
__global__ __launch_bounds__(128) void scan_top_kernel() {
    __shared__ int sh[128];
    int t = threadIdx.x;
    int v = (t < NBLK_SCAN) ? g_bsum[t] : 0;
    sh[t] = v;
    __syncthreads();
#pragma unroll
    for (int off = 1; off < 128; off <<= 1) {
        int x = (t >= off) ? sh[t - off] : 0;
        __syncthreads();
        sh[t] += x;
        __syncthreads();
    }
    if (t < NBLK_SCAN) g_bsumex[t] = sh[t] - v;
}

__global__ void fill_kernel(const int* __restrict__ src, const int* __restrict__ dst) {
    int e = blockIdx.x * blockDim.x + threadIdx.x;
    if (e >= NE) return;
    int c = dst[e];
    int pos = g_off[c] + g_bsumex[c >> 10] + atomicAdd(&g_fill[c], 1);
    g_adj[pos] = src[e];
}

// ---------------------------------------------------------------------------
// x (fp32) -> fp16 copy; each thread converts 8 floats
__global__ void x2h_kernel(const float* __restrict__ x) {
    int idx = blockIdx.x * blockDim.x + threadIdx.x;
    if (idx >= NN * DIN / 8) return;
    const float4* x4 = reinterpret_cast<const float4*>(x);
    float4 v0 = x4[idx * 2];
    float4 v1 = x4[idx * 2 + 1];
    uint4 o;
    __half2 h;
    h = __floats2half2_rn(v0.x, v0.y); o.x = *reinterpret_cast<uint32_t*>(&h);
    h = __floats2half2_rn(v0.z, v0.w); o.y = *reinterpret_cast<uint32_t*>(&h);
    h = __floats2half2_rn(v1.x, v1.y); o.z = *reinterpret_cast<uint32_t*>(&h);
    h = __floats2half2_rn(v1.z, v1.w); o.w = *reinterpret_cast<uint32_t*>(&h);
    reinterpret_cast<uint4*>(g_x16)[idx] = o;
}

// Weight transpose + fp32->fp16: Wt[n*K + k] = (half)W[k*256 + n]
__global__ void transpose_kernel(const float* __restrict__ W, __half* __restrict__ Wt, int K) {
    __shared__ float t[32][33];
    int kb = blockIdx.x * 32, nb = blockIdx.y * 32;
    int x = threadIdx.x, y = threadIdx.y;  // block (32, 8)
#pragma unroll
    for (int i = 0; i < 32; i += 8)
        t[y + i][x] = W[(size_t)(kb + y + i) * DH + nb + x];
    __syncthreads();
#pragma unroll
    for (int i = 0; i < 32; i += 8)
        Wt[(size_t)(nb + y + i) * K + kb + x] = __float2half(t[x][y + i]);
}

// ---------------------------------------------------------------------------
__device__ __forceinline__ void st_cs_v4(void* addr, uint4 v) {
    asm volatile("st.global.cs.v4.b32 [%0], {%1, %2, %3, %4};"
                 :: "l"(addr), "r"(v.x), "r"(v.y), "r"(v.z), "r"(v.w) : "memory");
}

// fp16 CSR gather aggregation (fp32 accumulate, fp16 out):
//   y[c] = dinv[c] * ( dinv[c]*in[c] + sum_{r in in(c)} dinv[r]*in[r] )
// 16 lanes per node; V4PR uint4 per row (16 -> D=128, 32 -> D=256).
template<int V4PR>
__global__ __launch_bounds__(256) void agg_f16_kernel(
    const __half* __restrict__ in, __half* __restrict__ outp)
{
    constexpr int VPL = V4PR / 16;
    int gtid = blockIdx.x * blockDim.x + threadIdx.x;
    int node = gtid >> 4;
    int lane = threadIdx.x & 15;
    if (node >= NN) return;

    const uint4* in8 = reinterpret_cast<const uint4*>(in);  // 8 halves per uint4
    size_t rb = (size_t)node * V4PR;
    float dc = g_dinv[node];

    float2 acc[VPL][4];
#pragma unroll
    for (int v = 0; v < VPL; v++) {
        uint4 s = in8[rb + v * 16 + lane];
        const __half2* h = reinterpret_cast<const __half2*>(&s);
#pragma unroll
        for (int p = 0; p < 4; p++) {
            float2 f = __half22float2(h[p]);
            acc[v][p] = make_float2(f.x * dc, f.y * dc);
        }
    }

    int start = g_off[node] + g_bsumex[node >> 10];
    int cnt = g_cin[node];
    int j = 0;
    for (; j + 4 <= cnt; j += 4) {
        int rr[4]; float ww[4];
#pragma unroll
        for (int u = 0; u < 4; u++) rr[u] = g_adj[start + j + u];
#pragma unroll
        for (int u = 0; u < 4; u++) ww[u] = g_dinv[rr[u]];
#pragma unroll
        for (int u = 0; u < 4; u++) {
            size_t nb = (size_t)rr[u] * V4PR;
#pragma unroll
            for (int v = 0; v < VPL; v++) {
                uint4 s = in8[nb + v * 16 + lane];
                const __half2* h = reinterpret_cast<const __half2*>(&s);
#pragma unroll
                for (int p = 0; p < 4; p++) {
                    float2 f = __half22float2(h[p]);
                    acc[v][p].x = fmaf(f.x, ww[u], acc[v][p].x);
                    acc[v][p].y = fmaf(f.y, ww[u], acc[v][p].y);
                }
            }
        }
    }
    for (; j < cnt; j++) {
        int r0 = g_adj[start + j];
        float w0 = g_dinv[r0];
        size_t nb = (size_t)r0 * V4PR;
#pragma unroll
        for (int v = 0; v < VPL; v++) {
            uint4 s = in8[nb + v * 16 + lane];
            const __half2* h = reinterpret_cast<const __half2*>(&s);
#pragma unroll
            for (int p = 0; p < 4; p++) {
                float2 f = __half22float2(h[p]);
                acc[v][p].x = fmaf(f.x, w0, acc[v][p].x);
                acc[v][p].y = fmaf(f.y, w0, acc[v][p].y);
            }
        }
    }

#pragma unroll
    for (int v = 0; v < VPL; v++) {
        uint4 o;
        uint32_t* ow = &o.x;
#pragma unroll
        for (int p = 0; p < 4; p++) {
            __half2 h = __floats2half2_rn(acc[v][p].x * dc, acc[v][p].y * dc);
            ow[p] = *reinterpret_cast<uint32_t*>(&h);
        }
        __half* addr = outp + (rb + (size_t)v * 16 + lane) * 8;
        st_cs_v4(addr, o);
    }
}

// ---------------------------------------------------------------------------
// fp16 tensor-core GEMM (mma.sync m16n8k16, fp32 accumulate):
//   C[m, colBase:+128] = relu(A[m,:K] @ Bt^T + bias), fp16 output
// CTA tile 128x128, BK=32, 8 warps (warp tile 64x32), double-buffered cp.async.
#define HPAD 40   // halves per padded smem row (80 bytes)

__device__ __forceinline__ void mma_f16(float* d, const uint32_t* a, const uint32_t* b) {
    asm volatile("mma.sync.aligned.m16n8k16.row.col.f32.f16.f16.f32 "
        "{%0,%1,%2,%3}, {%4,%5,%6,%7}, {%8,%9}, {%0,%1,%2,%3};\n"
        : "+f"(d[0]), "+f"(d[1]), "+f"(d[2]), "+f"(d[3])
        : "r"(a[0]), "r"(a[1]), "r"(a[2]), "r"(a[3]), "r"(b[0]), "r"(b[1]));
}

__global__ __launch_bounds__(256) void gemm_f16_kernel(
    const __half* __restrict__ A, const __half* __restrict__ Bt,
    const float* __restrict__ bias, __half* __restrict__ C,
    int M, int K)
{
    __shared__ __half As[2][128 * HPAD];
    __shared__ __half Bs[2][128 * HPAD];

    int tid  = threadIdx.x;
    int lane = tid & 31;
    int warp = tid >> 5;
    int warpM = warp & 1;    // 64 rows each
    int warpN = warp >> 1;   // 32 cols each
    int rowBase = blockIdx.y * 128;
    int colBase = blockIdx.x * 128;

    float acc[4][4][4];
#pragma unroll
    for (int mt = 0; mt < 4; mt++)
#pragma unroll
        for (int nt = 0; nt < 4; nt++)
#pragma unroll
            for (int i = 0; i < 4; i++) acc[mt][nt][i] = 0.0f;

    auto load_tiles = [&](int s, int k0) {
#pragma unroll
        for (int i = 0; i < 2; i++) {
            int idx = tid + i * 256;      // 0..511
            int row = idx >> 2;           // 0..127
            int c   = idx & 3;            // 16B chunk (8 halves)
            int gr = rowBase + row;
            const __half* srcA = A + (size_t)(gr < M ? gr : 0) * K + k0 + c * 8;
            uint32_t dstA = (uint32_t)__cvta_generic_to_shared(&As[s][row * HPAD + c * 8]);
            int sz = (gr < M) ? 16 : 0;
            asm volatile("cp.async.cg.shared.global [%0], [%1], 16, %2;\n"
                         :: "r"(dstA), "l"(srcA), "r"(sz));
            const __half* srcB = Bt + (size_t)(colBase + row) * K + k0 + c * 8;
            uint32_t dstB = (uint32_t)__cvta_generic_to_shared(&Bs[s][row * HPAD + c * 8]);
            asm volatile("cp.async.cg.shared.global [%0], [%1], 16;\n"
                         :: "r"(dstB), "l"(srcB));
        }
    };

    int r = lane >> 2;        // 0..7
    int kq = (lane & 3) * 2;  // 0,2,4,6

    auto compute = [&](int s) {
#pragma unroll
        for (int kg = 0; kg < 2; kg++) {
            int kb = kg * 16;
            uint32_t af[4][4], bf[4][2];
#pragma unroll
            for (int mt = 0; mt < 4; mt++) {
                int mb = warpM * 64 + mt * 16;
                const __half* base = &As[s][0];
                af[mt][0] = *reinterpret_cast<const uint32_t*>(base + (mb + r)     * HPAD + kb + kq);
                af[mt][1] = *reinterpret_cast<const uint32_t*>(base + (mb + r + 8) * HPAD + kb + kq);
                af[mt][2] = *reinterpret_cast<const uint32_t*>(base + (mb + r)     * HPAD + kb + kq + 8);
                af[mt][3] = *reinterpret_cast<const uint32_t*>(base + (mb + r + 8) * HPAD + kb + kq + 8);
            }
#pragma unroll
            for (int nt = 0; nt < 4; nt++) {
                int nb = warpN * 32 + nt * 8;
                const __half* base = &Bs[s][0];
                bf[nt][0] = *reinterpret_cast<const uint32_t*>(base + (nb + r) * HPAD + kb + kq);
                bf[nt][1] = *reinterpret_cast<const uint32_t*>(base + (nb + r) * HPAD + kb + kq + 8);
            }
#pragma unroll
            for (int mt = 0; mt < 4; mt++)
#pragma unroll
                for (int nt = 0; nt < 4; nt++)
                    mma_f16(acc[mt][nt], af[mt], bf[nt]);
        }
    };

    load_tiles(0, 0);
    asm volatile("cp.async.commit_group;\n");
    int buf = 0;
    for (int k0 = 32; k0 < K; k0 += 32) {
        load_tiles(buf ^ 1, k0);
        asm volatile("cp.async.commit_group;\n");
        asm volatile("cp.async.wait_group 1;\n");
        __syncthreads();
        compute(buf);
        __syncthreads();
        buf ^= 1;
    }
    asm volatile("cp.async.wait_group 0;\n");
    __syncthreads();
    compute(buf);

    // Epilogue: relu(acc + bias) -> fp16
    int c2 = (lane & 3) * 2;
    float2 bb[4];
#pragma unroll
    for (int nt = 0; nt < 4; nt++) {
        int gcol = colBase + warpN * 32 + nt * 8 + c2;
        bb[nt] = *reinterpret_cast<const float2*>(bias + gcol);
    }
#pragma unroll
    for (int mt = 0; mt < 4; mt++) {
        int grow0 = rowBase + warpM * 64 + mt * 16 + r;
        int grow1 = grow0 + 8;
#pragma unroll
        for (int nt = 0; nt < 4; nt++) {
            int gcol = colBase + warpN * 32 + nt * 8 + c2;
            if (grow0 < M) {
                __half2 h = __floats2half2_rn(fmaxf(acc[mt][nt][0] + bb[nt].x, 0.f),
                                              fmaxf(acc[mt][nt][1] + bb[nt].y, 0.f));
                *reinterpret_cast<uint32_t*>(C + (size_t)grow0 * DH + gcol) =
                    *reinterpret_cast<uint32_t*>(&h);
            }
            if (grow1 < M) {
                __half2 h = __floats2half2_rn(fmaxf(acc[mt][nt][2] + bb[nt].x, 0.f),
                                              fmaxf(acc[mt][nt][3] + bb[nt].y, 0.f));
                *reinterpret_cast<uint32_t*>(C + (size_t)grow1 * DH + gcol) =
                    *reinterpret_cast<uint32_t*>(&h);
            }
        }
    }
}

// ---------------------------------------------------------------------------
__global__ void zero_out_kernel(float* __restrict__ out) {
    int idx = blockIdx.x * blockDim.x + threadIdx.x;
    if (idx < NG * DH) out[idx] = 0.0f;
}

// Sorted-batch pool over fp16 a2; 128 threads = 128 half2 columns, fp32 accum.
#define POOL_CHUNK 128
__global__ __launch_bounds__(128) void pool_kernel(
    const int* __restrict__ batch, const __half* __restrict__ a, float* __restrict__ out)
{
    __shared__ int sb[POOL_CHUNK];
    int start = blockIdx.x * POOL_CHUNK;
    int cnt = min(POOL_CHUNK, NN - start);
    for (int i = threadIdx.x; i < cnt; i += 128) sb[i] = batch[start + i];
    __syncthreads();

    int d = threadIdx.x;  // half2 column 0..127
    const __half2* a2 = reinterpret_cast<const __half2*>(a);
    int curg = sb[0];
    float ax = 0.f, ay = 0.f;
    int run = 0;
    for (int n = 0; n < cnt; n++) {
        int g = sb[n];
        if (g != curg) {
            atomicAdd(&out[curg * DH + 2 * d], ax);
            atomicAdd(&out[curg * DH + 2 * d + 1], ay);
            if (d == 0) atomicAdd(&g_cnt[curg], run);
            ax = 0.f; ay = 0.f; run = 0; curg = g;
        }
        float2 f = __half22float2(a2[(size_t)(start + n) * 128 + d]);
        ax += f.x; ay += f.y;
        run++;
    }
    atomicAdd(&out[curg * DH + 2 * d], ax);
    atomicAdd(&out[curg * DH + 2 * d + 1], ay);
    if (d == 0) atomicAdd(&g_cnt[curg], run);
}

__global__ void divide_kernel(float* __restrict__ out) {
    int idx = blockIdx.x * blockDim.x + threadIdx.x;
    if (idx >= NG * DH) return;
    int g = idx >> 8;
    float c = (float)g_cnt[g];
    out[idx] = out[idx] / fmaxf(c, 1.0f);
}

// ---------------------------------------------------------------------------
extern "C" void kernel_launch(void* const* d_in, const int* in_sizes, int n_in,
                              void* d_out, int out_size)
{
    const float* x    = (const float*)d_in[0];   // [NN, 128]
    const int*   ei   = (const int*)  d_in[1];   // [2, NE]
    const int*   batch= (const int*)  d_in[2];   // [NN]
    const float* W1   = (const float*)d_in[3];   // [128, 256]
    const float* b1   = (const float*)d_in[4];   // [256]
    const float* W2   = (const float*)d_in[5];   // [256, 256]
    const float* b2   = (const float*)d_in[6];   // [256]
    float* out = (float*)d_out;                  // [64, 256]

    const int* src = ei;
    const int* dst = ei + NE;

    __half* d_x16; cudaGetSymbolAddress((void**)&d_x16, g_x16);
    __half* d_h;   cudaGetSymbolAddress((void**)&d_h, g_h);
    __half* d_a;   cudaGetSymbolAddress((void**)&d_a, g_a);
    __half* d_wt1; cudaGetSymbolAddress((void**)&d_wt1, g_wt1);
    __half* d_wt2; cudaGetSymbolAddress((void**)&d_wt2, g_wt2);

    // ---- input/weight fp16 conversions ----
    x2h_kernel<<<(NN * DIN / 8 + 255) / 256, 256>>>(x);
    transpose_kernel<<<dim3(DIN / 32, DH / 32), dim3(32, 8)>>>(W1, d_wt1, DIN);
    transpose_kernel<<<dim3(DH / 32, DH / 32), dim3(32, 8)>>>(W2, d_wt2, DH);

    // ---- CSR build + normalization ----
    zero_kernel<<<(NN + 255) / 256, 256>>>();
    hist_kernel<<<(NE + 255) / 256, 256>>>(dst);
    scan_block_kernel<<<NBLK_SCAN, 256>>>();
    scan_top_kernel<<<1, 128>>>();
    fill_kernel<<<(NE + 255) / 256, 256>>>(src, dst);

    dim3 gemmGrid(2, (NN + 127) / 128);   // (2, 782)
    int aggGrid = (NN * 16 + 255) / 256;

    // ---- Layer 1: agg(x16) D=128, GEMM fp16 -> a1 (fp16) ----
    agg_f16_kernel<16><<<aggGrid, 256>>>(d_x16, d_h);
    gemm_f16_kernel<<<gemmGrid, 256>>>(d_h, d_wt1, b1, d_a, NN, DIN);

    // ---- Layer 2: agg(a1) D=256, GEMM fp16 -> a2 (fp16) ----
    agg_f16_kernel<32><<<aggGrid, 256>>>(d_a, d_h);
    gemm_f16_kernel<<<gemmGrid, 256>>>(d_h, d_wt2, b2, d_a, NN, DH);

    // ---- Global mean pool ----
    zero_out_kernel<<<(NG * DH + 255) / 256, 256>>>(out);
    pool_kernel<<<(NN + POOL_CHUNK - 1) / POOL_CHUNK, 128>>>(batch, d_a, out);
    divide_kernel<<<(NG * DH + 255) / 256, 256>>>(out);
}

// round 8
// speedup vs baseline: 5.6776x; 1.0615x over previous
#include <cuda_runtime.h>
#include <cuda_fp16.h>
#include <cstdint>

// Problem constants (fixed by the dataset)
constexpr int NN   = 100000;   // nodes
constexpr int NE   = 1600000;  // edges
constexpr int NG   = 64;       // graphs
constexpr int DIN  = 128;
constexpr int DH   = 256;      // hidden == out dim

constexpr int SCHUNK = 1024;
constexpr int NBLK_SCAN = (NN + SCHUNK - 1) / SCHUNK;  // 98

// Scratch (device globals — no allocations allowed)
__device__ __align__(16) float  g_dinv[NN];
__device__ __align__(16) __half g_x16[(size_t)NN * DIN]; // x' = dinv*x (fp16)
__device__ __align__(16) __half g_h [(size_t)NN * DH];   // agg outputs y1/y2 (fp16)
__device__ __align__(16) __half g_a [(size_t)NN * DH];   // GEMM outputs a1'/a2 (fp16)
__device__ __align__(16) __half g_wt1[DH * DIN];         // W1^T fp16 [256][128]
__device__ __align__(16) __half g_wt2[DH * DH];          // W2^T fp16 [256][256]
__device__ int g_cin [NN];
__device__ int g_off [NN];
__device__ int g_bsum[NBLK_SCAN];
__device__ int g_bsumex[NBLK_SCAN];
__device__ int g_fill[NN];
__device__ int g_adj [NE];
__device__ int g_cnt [NG];

// ---------------------------------------------------------------------------
__global__ void zero_kernel(float* __restrict__ out) {
    int i = blockIdx.x * blockDim.x + threadIdx.x;
    if (i < NN) { g_cin[i] = 0; g_fill[i] = 0; }
    if (i < NG) g_cnt[i] = 0;
    if (i < NG * DH) out[i] = 0.0f;
}

__global__ void hist_kernel(const int* __restrict__ dst) {
    int e = blockIdx.x * blockDim.x + threadIdx.x;
    if (e < NE) atomicAdd(&g_cin[dst[e]], 1);
}

// Block scan over 1024-element chunks + fused dinv computation
__global__ __launch_bounds__(256) void scan_block_kernel() {
    __shared__ int st[256];
    int base = blockIdx.x * SCHUNK;
    int tid = threadIdx.x;
    int v[4], pre[4];
    int s = 0;
#pragma unroll
    for (int i = 0; i < 4; i++) {
        int idx = base + tid * 4 + i;
        v[i] = (idx < NN) ? g_cin[idx] : 0;
        if (idx < NN) g_dinv[idx] = rsqrtf((float)(v[i] + 1));
        pre[i] = s;
        s += v[i];
    }
    st[tid] = s;
    __syncthreads();
#pragma unroll
    for (int off = 1; off < 256; off <<= 1) {
        int x = (tid >= off) ? st[tid - off] : 0;
        __syncthreads();
        st[tid] += x;
        __syncthreads();
    }
    int excl = st[tid] - s;
#pragma unroll
    for (int i = 0; i < 4; i++) {
        int idx = base + tid * 4 + i;
        if (idx < NN) g_off[idx] = excl + pre[i];
    }
    if (tid == 255) g_bsum[blockIdx.x] = st[255];
}

// Parallel exclusive scan of the 98 chunk totals (one block, 128 threads)
__global__ __launch_bounds__(128) void scan_top_kernel() {
    __shared__ int sh[128];
    int t = threadIdx.x;
    int v = (t < NBLK_SCAN) ? g_bsum[t] : 0;
    sh[t] = v;
    __syncthreads();
#pragma unroll
    for (int off = 1; off < 128; off <<= 1) {
        int x = (t >= off) ? sh[t - off] : 0;
        __syncthreads();
        sh[t] += x;
        __syncthreads();
    }
    if (t < NBLK_SCAN) g_bsumex[t] = sh[t] - v;
}

__global__ void fill_kernel(const int* __restrict__ src, const int* __restrict__ dst) {
    int e = blockIdx.x * blockDim.x + threadIdx.x;
    if (e >= NE) return;
    int c = dst[e];
    int pos = g_off[c] + g_bsumex[c >> 10] + atomicAdd(&g_fill[c], 1);
    g_adj[pos] = src[e];
}

// ---------------------------------------------------------------------------
// x (fp32) -> x' = dinv[n]*x fp16; each thread converts 8 floats
__global__ void x2h_kernel(const float* __restrict__ x) {
    int idx = blockIdx.x * blockDim.x + threadIdx.x;
    if (idx >= NN * DIN / 8) return;
    float s = g_dinv[idx >> 4];           // 16 chunks of 8 per 128-dim row
    const float4* x4 = reinterpret_cast<const float4*>(x);
    float4 v0 = x4[idx * 2];
    float4 v1 = x4[idx * 2 + 1];
    uint4 o;
    __half2 h;
    h = __floats2half2_rn(v0.x * s, v0.y * s); o.x = *reinterpret_cast<uint32_t*>(&h);
    h = __floats2half2_rn(v0.z * s, v0.w * s); o.y = *reinterpret_cast<uint32_t*>(&h);
    h = __floats2half2_rn(v1.x * s, v1.y * s); o.z = *reinterpret_cast<uint32_t*>(&h);
    h = __floats2half2_rn(v1.z * s, v1.w * s); o.w = *reinterpret_cast<uint32_t*>(&h);
    reinterpret_cast<uint4*>(g_x16)[idx] = o;
}

// Weight transpose + fp32->fp16: Wt[n*K + k] = (half)W[k*256 + n]
__global__ void transpose_kernel(const float* __restrict__ W, __half* __restrict__ Wt, int K) {
    __shared__ float t[32][33];
    int kb = blockIdx.x * 32, nb = blockIdx.y * 32;
    int x = threadIdx.x, y = threadIdx.y;  // block (32, 8)
#pragma unroll
    for (int i = 0; i < 32; i += 8)
        t[y + i][x] = W[(size_t)(kb + y + i) * DH + nb + x];
    __syncthreads();
#pragma unroll
    for (int i = 0; i < 32; i += 8)
        Wt[(size_t)(nb + y + i) * K + kb + x] = __float2half(t[x][y + i]);
}

// ---------------------------------------------------------------------------
__device__ __forceinline__ void st_cs_v4(void* addr, uint4 v) {
    asm volatile("st.global.cs.v4.b32 [%0], {%1, %2, %3, %4};"
                 :: "l"(addr), "r"(v.x), "r"(v.y), "r"(v.z), "r"(v.w) : "memory");
}

// fp16 CSR gather over pre-scaled rows (fp32 accumulate, fp16 out):
//   y[c] = dinv[c] * ( row'[c] + sum_{r in in(c)} row'[r] )
// LPG lanes per node, 2 uint4 (16 halves) per lane. Row = LPG*32 bytes.
template<int LPG>
__global__ __launch_bounds__(256) void agg_kernel(
    const __half* __restrict__ in, __half* __restrict__ outp)
{
    constexpr int V4PR = 2 * LPG;   // uint4 per row (16 -> D=128, 32 -> D=256)
    int gtid = blockIdx.x * blockDim.x + threadIdx.x;
    int node = gtid / LPG;
    int lane = threadIdx.x & (LPG - 1);
    if (node >= NN) return;

    const uint4* in8 = reinterpret_cast<const uint4*>(in);
    size_t rb = (size_t)node * V4PR;

    float2 acc[2][4];
#pragma unroll
    for (int v = 0; v < 2; v++) {
        uint4 s = in8[rb + v * LPG + lane];
        const __half2* h = reinterpret_cast<const __half2*>(&s);
#pragma unroll
        for (int p = 0; p < 4; p++) acc[v][p] = __half22float2(h[p]);
    }

    int start = g_off[node] + g_bsumex[node >> 10];
    int cnt = g_cin[node];
    int j = 0;
    for (; j + 4 <= cnt; j += 4) {
        int rr[4];
#pragma unroll
        for (int u = 0; u < 4; u++) rr[u] = g_adj[start + j + u];
#pragma unroll
        for (int u = 0; u < 4; u++) {
            size_t nb = (size_t)rr[u] * V4PR;
#pragma unroll
            for (int v = 0; v < 2; v++) {
                uint4 s = in8[nb + v * LPG + lane];
                const __half2* h = reinterpret_cast<const __half2*>(&s);
#pragma unroll
                for (int p = 0; p < 4; p++) {
                    float2 f = __half22float2(h[p]);
                    acc[v][p].x += f.x;
                    acc[v][p].y += f.y;
                }
            }
        }
    }
    for (; j < cnt; j++) {
        int r0 = g_adj[start + j];
        size_t nb = (size_t)r0 * V4PR;
#pragma unroll
        for (int v = 0; v < 2; v++) {
            uint4 s = in8[nb + v * LPG + lane];
            const __half2* h = reinterpret_cast<const __half2*>(&s);
#pragma unroll
            for (int p = 0; p < 4; p++) {
                float2 f = __half22float2(h[p]);
                acc[v][p].x += f.x;
                acc[v][p].y += f.y;
            }
        }
    }

    float dc = g_dinv[node];
#pragma unroll
    for (int v = 0; v < 2; v++) {
        uint4 o;
        uint32_t* ow = &o.x;
#pragma unroll
        for (int p = 0; p < 4; p++) {
            __half2 h = __floats2half2_rn(acc[v][p].x * dc, acc[v][p].y * dc);
            ow[p] = *reinterpret_cast<uint32_t*>(&h);
        }
        __half* addr = outp + (rb + (size_t)v * LPG + lane) * 8;
        st_cs_v4(addr, o);
    }
}

// ---------------------------------------------------------------------------
// fp16 tensor-core GEMM (mma.sync m16n8k16, fp32 accumulate):
//   C[m, colBase:+128] = scale_m * relu(A[m,:K] @ Bt^T + bias), fp16 output
// SCALE: multiply rows by dinv[m] (pre-scaling for the next aggregation).
#define HPAD 40   // halves per padded smem row (80 bytes)

__device__ __forceinline__ void mma_f16(float* d, const uint32_t* a, const uint32_t* b) {
    asm volatile("mma.sync.aligned.m16n8k16.row.col.f32.f16.f16.f32 "
        "{%0,%1,%2,%3}, {%4,%5,%6,%7}, {%8,%9}, {%0,%1,%2,%3};\n"
        : "+f"(d[0]), "+f"(d[1]), "+f"(d[2]), "+f"(d[3])
        : "r"(a[0]), "r"(a[1]), "r"(a[2]), "r"(a[3]), "r"(b[0]), "r"(b[1]));
}

template<bool SCALE>
__global__ __launch_bounds__(256) void gemm_f16_kernel(
    const __half* __restrict__ A, const __half* __restrict__ Bt,
    const float* __restrict__ bias, __half* __restrict__ C,
    int M, int K)
{
    __shared__ __half As[2][128 * HPAD];
    __shared__ __half Bs[2][128 * HPAD];

    int tid  = threadIdx.x;
    int lane = tid & 31;
    int warp = tid >> 5;
    int warpM = warp & 1;    // 64 rows each
    int warpN = warp >> 1;   // 32 cols each
    int rowBase = blockIdx.y * 128;
    int colBase = blockIdx.x * 128;

    float acc[4][4][4];
#pragma unroll
    for (int mt = 0; mt < 4; mt++)
#pragma unroll
        for (int nt = 0; nt < 4; nt++)
#pragma unroll
            for (int i = 0; i < 4; i++) acc[mt][nt][i] = 0.0f;

    auto load_tiles = [&](int s, int k0) {
#pragma unroll
        for (int i = 0; i < 2; i++) {
            int idx = tid + i * 256;      // 0..511
            int row = idx >> 2;           // 0..127
            int c   = idx & 3;            // 16B chunk (8 halves)
            int gr = rowBase + row;
            const __half* srcA = A + (size_t)(gr < M ? gr : 0) * K + k0 + c * 8;
            uint32_t dstA = (uint32_t)__cvta_generic_to_shared(&As[s][row * HPAD + c * 8]);
            int sz = (gr < M) ? 16 : 0;
            asm volatile("cp.async.cg.shared.global [%0], [%1], 16, %2;\n"
                         :: "r"(dstA), "l"(srcA), "r"(sz));
            const __half* srcB = Bt + (size_t)(colBase + row) * K + k0 + c * 8;
            uint32_t dstB = (uint32_t)__cvta_generic_to_shared(&Bs[s][row * HPAD + c * 8]);
            asm volatile("cp.async.cg.shared.global [%0], [%1], 16;\n"
                         :: "r"(dstB), "l"(srcB));
        }
    };

    int r = lane >> 2;        // 0..7
    int kq = (lane & 3) * 2;  // 0,2,4,6

    auto compute = [&](int s) {
#pragma unroll
        for (int kg = 0; kg < 2; kg++) {
            int kb = kg * 16;
            uint32_t af[4][4], bf[4][2];
#pragma unroll
            for (int mt = 0; mt < 4; mt++) {
                int mb = warpM * 64 + mt * 16;
                const __half* base = &As[s][0];
                af[mt][0] = *reinterpret_cast<const uint32_t*>(base + (mb + r)     * HPAD + kb + kq);
                af[mt][1] = *reinterpret_cast<const uint32_t*>(base + (mb + r + 8) * HPAD + kb + kq);
                af[mt][2] = *reinterpret_cast<const uint32_t*>(base + (mb + r)     * HPAD + kb + kq + 8);
                af[mt][3] = *reinterpret_cast<const uint32_t*>(base + (mb + r + 8) * HPAD + kb + kq + 8);
            }
#pragma unroll
            for (int nt = 0; nt < 4; nt++) {
                int nb = warpN * 32 + nt * 8;
                const __half* base = &Bs[s][0];
                bf[nt][0] = *reinterpret_cast<const uint32_t*>(base + (nb + r) * HPAD + kb + kq);
                bf[nt][1] = *reinterpret_cast<const uint32_t*>(base + (nb + r) * HPAD + kb + kq + 8);
            }
#pragma unroll
            for (int mt = 0; mt < 4; mt++)
#pragma unroll
                for (int nt = 0; nt < 4; nt++)
                    mma_f16(acc[mt][nt], af[mt], bf[nt]);
        }
    };

    load_tiles(0, 0);
    asm volatile("cp.async.commit_group;\n");
    int buf = 0;
    for (int k0 = 32; k0 < K; k0 += 32) {
        load_tiles(buf ^ 1, k0);
        asm volatile("cp.async.commit_group;\n");
        asm volatile("cp.async.wait_group 1;\n");
        __syncthreads();
        compute(buf);
        __syncthreads();
        buf ^= 1;
    }
    asm volatile("cp.async.wait_group 0;\n");
    __syncthreads();
    compute(buf);

    // Epilogue: scale_m * relu(acc + bias) -> fp16
    int c2 = (lane & 3) * 2;
    float2 bb[4];
#pragma unroll
    for (int nt = 0; nt < 4; nt++) {
        int gcol = colBase + warpN * 32 + nt * 8 + c2;
        bb[nt] = *reinterpret_cast<const float2*>(bias + gcol);
    }
#pragma unroll
    for (int mt = 0; mt < 4; mt++) {
        int grow0 = rowBase + warpM * 64 + mt * 16 + r;
        int grow1 = grow0 + 8;
        float s0 = 1.0f, s1 = 1.0f;
        if (SCALE) {
            s0 = (grow0 < M) ? g_dinv[grow0] : 1.0f;
            s1 = (grow1 < M) ? g_dinv[grow1] : 1.0f;
        }
#pragma unroll
        for (int nt = 0; nt < 4; nt++) {
            int gcol = colBase + warpN * 32 + nt * 8 + c2;
            if (grow0 < M) {
                __half2 h = __floats2half2_rn(fmaxf(acc[mt][nt][0] + bb[nt].x, 0.f) * s0,
                                              fmaxf(acc[mt][nt][1] + bb[nt].y, 0.f) * s0);
                *reinterpret_cast<uint32_t*>(C + (size_t)grow0 * DH + gcol) =
                    *reinterpret_cast<uint32_t*>(&h);
            }
            if (grow1 < M) {
                __half2 h = __floats2half2_rn(fmaxf(acc[mt][nt][2] + bb[nt].x, 0.f) * s1,
                                              fmaxf(acc[mt][nt][3] + bb[nt].y, 0.f) * s1);
                *reinterpret_cast<uint32_t*>(C + (size_t)grow1 * DH + gcol) =
                    *reinterpret_cast<uint32_t*>(&h);
            }
        }
    }
}

// ---------------------------------------------------------------------------
// Sorted-batch pool over fp16 a2; 128 threads = 128 half2 columns, fp32 accum.
#define POOL_CHUNK 128
__global__ __launch_bounds__(128) void pool_kernel(
    const int* __restrict__ batch, const __half* __restrict__ a, float* __restrict__ out)
{
    __shared__ int sb[POOL_CHUNK];
    int start = blockIdx.x * POOL_CHUNK;
    int cnt = min(POOL_CHUNK, NN - start);
    for (int i = threadIdx.x; i < cnt; i += 128) sb[i] = batch[start + i];
    __syncthreads();

    int d = threadIdx.x;  // half2 column 0..127
    const __half2* a2 = reinterpret_cast<const __half2*>(a);
    int curg = sb[0];
    float ax = 0.f, ay = 0.f;
    int run = 0;
    for (int n = 0; n < cnt; n++) {
        int g = sb[n];
        if (g != curg) {
            atomicAdd(&out[curg * DH + 2 * d], ax);
            atomicAdd(&out[curg * DH + 2 * d + 1], ay);
            if (d == 0) atomicAdd(&g_cnt[curg], run);
            ax = 0.f; ay = 0.f; run = 0; curg = g;
        }
        float2 f = __half22float2(a2[(size_t)(start + n) * 128 + d]);
        ax += f.x; ay += f.y;
        run++;
    }
    atomicAdd(&out[curg * DH + 2 * d], ax);
    atomicAdd(&out[curg * DH + 2 * d + 1], ay);
    if (d == 0) atomicAdd(&g_cnt[curg], run);
}

__global__ void divide_kernel(float* __restrict__ out) {
    int idx = blockIdx.x * blockDim.x + threadIdx.x;
    if (idx >= NG * DH) return;
    int g = idx >> 8;
    float c = (float)g_cnt[g];
    out[idx] = out[idx] / fmaxf(c, 1.0f);
}

// ---------------------------------------------------------------------------
extern "C" void kernel_launch(void* const* d_in, const int* in_sizes, int n_in,
                              void* d_out, int out_size)
{
    const float* x    = (const float*)d_in[0];   // [NN, 128]
    const int*   ei   = (const int*)  d_in[1];   // [2, NE]
    const int*   batch= (const int*)  d_in[2];   // [NN]
    const float* W1   = (const float*)d_in[3];   // [128, 256]
    const float* b1   = (const float*)d_in[4];   // [256]
    const float* W2   = (const float*)d_in[5];   // [256, 256]
    const float* b2   = (const float*)d_in[6];   // [256]
    float* out = (float*)d_out;                  // [64, 256]

    const int* src = ei;
    const int* dst = ei + NE;

    __half* d_x16; cudaGetSymbolAddress((void**)&d_x16, g_x16);
    __half* d_h;   cudaGetSymbolAddress((void**)&d_h, g_h);
    __half* d_a;   cudaGetSymbolAddress((void**)&d_a, g_a);
    __half* d_wt1; cudaGetSymbolAddress((void**)&d_wt1, g_wt1);
    __half* d_wt2; cudaGetSymbolAddress((void**)&d_wt2, g_wt2);

    // ---- weight conversions (no CSR dependency) ----
    transpose_kernel<<<dim3(DIN / 32, DH / 32), dim3(32, 8)>>>(W1, d_wt1, DIN);
    transpose_kernel<<<dim3(DH / 32, DH / 32), dim3(32, 8)>>>(W2, d_wt2, DH);

    // ---- CSR build + normalization ----
    zero_kernel<<<(NN + 255) / 256, 256>>>(out);
    hist_kernel<<<(NE + 255) / 256, 256>>>(dst);
    scan_block_kernel<<<NBLK_SCAN, 256>>>();
    scan_top_kernel<<<1, 128>>>();
    x2h_kernel<<<(NN * DIN / 8 + 255) / 256, 256>>>(x);   // needs dinv
    fill_kernel<<<(NE + 255) / 256, 256>>>(src, dst);

    dim3 gemmGrid(2, (NN + 127) / 128);   // (2, 782)

    // ---- Layer 1: agg(x') D=128, GEMM fp16 -> a1' = dinv*relu(...) ----
    agg_kernel<8><<<(NN * 8 + 255) / 256, 256>>>(d_x16, d_h);
    gemm_f16_kernel<true><<<gemmGrid, 256>>>(d_h, d_wt1, b1, d_a, NN, DIN);

    // ---- Layer 2: agg(a1') D=256, GEMM fp16 -> a2 ----
    agg_kernel<16><<<(NN * 16 + 255) / 256, 256>>>(d_a, d_h);
    gemm_f16_kernel<false><<<gemmGrid, 256>>>(d_h, d_wt2, b2, d_a, NN, DH);

    // ---- Global mean pool ----
    pool_kernel<<<(NN + POOL_CHUNK - 1) / POOL_CHUNK, 128>>>(batch, d_a, out);
    divide_kernel<<<(NG * DH + 255) / 256, 256>>>(out);
}